// round 2
// baseline (speedup 1.0000x reference)
#include <cuda_runtime.h>
#include <math.h>
#include <stdint.h>

// Problem dims
#define NB 16
#define NP 8192
#define NG 512
#define NK 32
#define ND 384
#define NL 12
#define NH 6
#define BGc (NB*NG)      /* 8192 */
#define M1  (BGc*NK)     /* 262144 */

// ---------------- scratch layout (single __device__ BSS array) ----------------
constexpr size_t O_H1  = 0;
constexpr size_t O_F   = O_H1  + (size_t)M1*128;
constexpr size_t O_H3  = O_F   + (size_t)M1*256;
constexpr size_t O_F4  = O_H3  + (size_t)M1*512;
constexpr size_t O_FG  = O_F4  + (size_t)M1*384;
constexpr size_t O_X   = O_FG  + (size_t)BGc*256;
constexpr size_t O_XIN = O_X   + (size_t)BGc*384;
constexpr size_t O_HLN = O_XIN + (size_t)BGc*384;
constexpr size_t O_OB  = O_HLN + (size_t)BGc*384;
constexpr size_t O_POS = O_OB  + (size_t)BGc*384;
constexpr size_t O_QKV = O_POS + (size_t)BGc*384;
constexpr size_t O_SC  = O_QKV + (size_t)BGc*1152;
constexpr size_t O_FF  = O_SC  + (size_t)96*512*512;
constexpr size_t O_CTR = O_FF  + (size_t)BGc*1536;
constexpr size_t O_ST  = O_CTR + (size_t)BGc*3;
constexpr size_t SCRATCH_TOTAL = O_ST + 4096;

__device__ float g_scratch[SCRATCH_TOTAL];

__device__ __forceinline__ float gelu_f(float x) {
    return 0.5f * x * (1.0f + erff(x * 0.70710678118654752f));
}

// ---------------- zero / add / maxk ----------------
__global__ void zero_kernel(float* p, int n) {
    int i = blockIdx.x * blockDim.x + threadIdx.x;
    if (i < n) p[i] = 0.0f;
}

__global__ void add_kernel(const float* __restrict__ a, const float* __restrict__ b,
                           float* __restrict__ c, int n) {
    int i = blockIdx.x * blockDim.x + threadIdx.x;
    if (i < n) c[i] = a[i] + b[i];
}

// max over K=32 rows: in [(8192*32), C] -> out [8192, C]
__global__ void maxk_kernel(const float* __restrict__ in, float* __restrict__ out,
                            int C, int total) {
    int idx = blockIdx.x * blockDim.x + threadIdx.x;
    if (idx >= total) return;
    int r = idx / C, c = idx - r * C;
    const float* p = in + ((size_t)r * 32) * C + c;
    float m = p[0];
#pragma unroll
    for (int t = 1; t < 32; t++) m = fmaxf(m, p[(size_t)t * C]);
    out[idx] = m;
}

// ---------------- FPS: one block per batch, sequential 511-step argmax scan ----------------
__global__ void __launch_bounds__(1024) fps_kernel(const float* __restrict__ pts,
                                                   float* __restrict__ ctr,
                                                   float* __restrict__ ctr_out) {
    int b = blockIdx.x;
    int tid = threadIdx.x;
    const float* P = pts + (size_t)b * NP * 3;
    float px[8], py[8], pz[8], dl[8];
#pragma unroll
    for (int t = 0; t < 8; t++) {
        int j = tid + t * 1024;
        px[t] = P[j * 3 + 0]; py[t] = P[j * 3 + 1]; pz[t] = P[j * 3 + 2];
        dl[t] = 1e10f;
    }
    __shared__ float lastp[3];
    __shared__ float sval[1024];
    __shared__ int   sidx[1024];
    if (tid == 0) {
        lastp[0] = P[0]; lastp[1] = P[1]; lastp[2] = P[2];
        size_t co = (size_t)b * NG * 3;
        ctr[co] = P[0]; ctr[co + 1] = P[1]; ctr[co + 2] = P[2];
        ctr_out[co] = P[0]; ctr_out[co + 1] = P[1]; ctr_out[co + 2] = P[2];
    }
    __syncthreads();
    for (int s = 1; s < NG; s++) {
        float lx = lastp[0], ly = lastp[1], lz = lastp[2];
        float bv = -1.0f; int bi = 0;
#pragma unroll
        for (int t = 0; t < 8; t++) {
            float dx = __fsub_rn(px[t], lx);
            float dy = __fsub_rn(py[t], ly);
            float dz = __fsub_rn(pz[t], lz);
            float d = __fadd_rn(__fadd_rn(__fmul_rn(dx, dx), __fmul_rn(dy, dy)),
                                __fmul_rn(dz, dz));
            float nd = fminf(dl[t], d);
            dl[t] = nd;
            if (nd > bv) { bv = nd; bi = tid + t * 1024; }
        }
        sval[tid] = bv; sidx[tid] = bi;
        __syncthreads();
        for (int o = 512; o; o >>= 1) {
            if (tid < o) {
                float v2 = sval[tid + o]; int i2 = sidx[tid + o];
                if (v2 > sval[tid] || (v2 == sval[tid] && i2 < sidx[tid])) {
                    sval[tid] = v2; sidx[tid] = i2;
                }
            }
            __syncthreads();
        }
        if (tid == 0) {
            int nxt = sidx[0];
            float qx = P[nxt * 3], qy = P[nxt * 3 + 1], qz = P[nxt * 3 + 2];
            lastp[0] = qx; lastp[1] = qy; lastp[2] = qz;
            size_t co = ((size_t)b * NG + s) * 3;
            ctr[co] = qx; ctr[co + 1] = qy; ctr[co + 2] = qz;
            ctr_out[co] = qx; ctr_out[co + 1] = qy; ctr_out[co + 2] = qz;
        }
        __syncthreads();
    }
}

// ---------------- KNN: one block per (b,g); smem d2, 32 exact argmins ----------------
// d2 must be bit-identical to the reference:
//   p2  = rn(rn(rn(px*px)+rn(py*py))+rn(pz*pz))          (elementwise square + reduce)
//   dot = fma(cz,pz, fma(cy,py, rn(cx*px)))              (K=3 FMA accumulation, acc=0)
//   d2  = rn(rn(c2+p2) - 2*dot)                          (2*dot exact)
__global__ void __launch_bounds__(256) knn_kernel(const float* __restrict__ pts,
                                                  const float* __restrict__ ctr,
                                                  float* __restrict__ nbr_out) {
    int bg = blockIdx.x;
    int b = bg >> 9;
    const float* P = pts + (size_t)b * NP * 3;
    float cx = ctr[bg * 3 + 0], cy = ctr[bg * 3 + 1], cz = ctr[bg * 3 + 2];
    float c2 = __fadd_rn(__fadd_rn(__fmul_rn(cx, cx), __fmul_rn(cy, cy)), __fmul_rn(cz, cz));
    __shared__ float d2s[NP];
    int tid = threadIdx.x;
    for (int j = tid; j < NP; j += 256) {
        float px = P[j * 3], py = P[j * 3 + 1], pz = P[j * 3 + 2];
        float p2 = __fadd_rn(__fadd_rn(__fmul_rn(px, px), __fmul_rn(py, py)), __fmul_rn(pz, pz));
        float dot = __fmaf_rn(cz, pz, __fmaf_rn(cy, py, __fmul_rn(cx, px)));
        d2s[j] = __fsub_rn(__fadd_rn(c2, p2), __fmul_rn(2.0f, dot));
    }
    __syncthreads();
    __shared__ float rv[256];
    __shared__ int ri[256];
    __shared__ int chosen[NK];
    for (int sel = 0; sel < NK; sel++) {
        float bv = 3.4e38f; int bi = 0x7fffffff;
        for (int j = tid; j < NP; j += 256) {
            float v = d2s[j];
            if (v < bv) { bv = v; bi = j; }
        }
        rv[tid] = bv; ri[tid] = bi;
        __syncthreads();
        for (int o = 128; o; o >>= 1) {
            if (tid < o) {
                float v2 = rv[tid + o]; int i2 = ri[tid + o];
                if (v2 < rv[tid] || (v2 == rv[tid] && i2 < ri[tid])) {
                    rv[tid] = v2; ri[tid] = i2;
                }
            }
            __syncthreads();
        }
        if (tid == 0) { chosen[sel] = ri[0]; d2s[ri[0]] = 3.4e38f; }
        __syncthreads();
    }
    if (tid < NK) {
        int j = chosen[tid];
        size_t o = ((size_t)bg * NK + tid) * 3;
        nbr_out[o + 0] = P[j * 3 + 0] - cx;
        nbr_out[o + 1] = P[j * 3 + 1] - cy;
        nbr_out[o + 2] = P[j * 3 + 2] - cz;
    }
}

// ---------------- encoder first linear 3->128 ----------------
__global__ void enc1_kernel(const float* __restrict__ nbr, const float* __restrict__ w1,
                            const float* __restrict__ b1, float* __restrict__ h1) {
    size_t idx = (size_t)blockIdx.x * blockDim.x + threadIdx.x;
    if (idx >= (size_t)M1 * 128) return;
    size_t i = idx >> 7;
    int c = (int)(idx & 127);
    float x0 = nbr[i * 3], x1 = nbr[i * 3 + 1], x2 = nbr[i * 3 + 2];
    h1[idx] = x0 * w1[c] + x1 * w1[128 + c] + x2 * w1[256 + c] + b1[c];
}

// ---------------- BN stats ----------------
__global__ void bnstats_kernel(const float* __restrict__ h, int C,
                               float* __restrict__ s1, float* __restrict__ s2) {
    int c = threadIdx.x;
    size_t r0 = (size_t)blockIdx.x * 512;
    const float* p = h + r0 * C + c;
    float a = 0.f, q = 0.f;
    for (int r = 0; r < 512; r++) {
        float v = p[(size_t)r * C];
        a += v; q += v * v;
    }
    atomicAdd(&s1[c], a);
    atomicAdd(&s2[c], q);
}

__global__ void bnfin_kernel(const float* __restrict__ s1, const float* __restrict__ s2,
                             float invM, const float* __restrict__ g, const float* __restrict__ b,
                             float* __restrict__ scale, float* __restrict__ shift) {
    int c = threadIdx.x;
    float mean = s1[c] * invM;
    float var = s2[c] * invM - mean * mean;
    float r = rsqrtf(var + 1e-5f);
    float sc = g[c] * r;
    scale[c] = sc;
    shift[c] = b[c] - mean * sc;
}

// ---------------- generic SGEMM 128x128x8, 8x8 per thread ----------------
// AMODE 0: plain A[M,K]; 1: relu(A*scale[k]+shift[k]); 2: concat(fg[row/32], f[row]) K=512
// EPI   0: +bias; 1: +bias+res; 2: gelu(+bias)
template <int AMODE, int EPI>
__global__ void __launch_bounds__(256) gemm128_kernel(
    const float* __restrict__ A, const float* __restrict__ W,
    const float* __restrict__ bias, const float* __restrict__ res,
    float* __restrict__ C, int M, int N, int K,
    const float* __restrict__ q0, const float* __restrict__ q1) {
    __shared__ float As[8][132];
    __shared__ float Ws[8][128];
    const int tid = threadIdx.x;
    const int tx = tid & 15, ty = tid >> 4;
    const int row0 = blockIdx.y << 7, col0 = blockIdx.x << 7;
    const int am = tid >> 1, ak = (tid & 1) << 2;
    const int wr = tid >> 5, wc = (tid & 31) << 2;
    const int grow = row0 + am;
    float acc[8][8];
#pragma unroll
    for (int i = 0; i < 8; i++)
#pragma unroll
        for (int j = 0; j < 8; j++) acc[i][j] = 0.f;

    for (int k0 = 0; k0 < K; k0 += 8) {
        int kg = k0 + ak;
        float4 av;
        if (AMODE == 0) {
            av = *(const float4*)(A + (size_t)grow * K + kg);
        } else if (AMODE == 1) {
            av = *(const float4*)(A + (size_t)grow * K + kg);
            av.x = fmaxf(fmaf(av.x, q0[kg + 0], q1[kg + 0]), 0.f);
            av.y = fmaxf(fmaf(av.y, q0[kg + 1], q1[kg + 1]), 0.f);
            av.z = fmaxf(fmaf(av.z, q0[kg + 2], q1[kg + 2]), 0.f);
            av.w = fmaxf(fmaf(av.w, q0[kg + 3], q1[kg + 3]), 0.f);
        } else {
            const float* src = (kg < 256) ? (q0 + (((size_t)(grow >> 5)) << 8) + kg)
                                          : (A + (((size_t)grow) << 8) + (kg - 256));
            av = *(const float4*)src;
        }
        As[ak + 0][am] = av.x; As[ak + 1][am] = av.y;
        As[ak + 2][am] = av.z; As[ak + 3][am] = av.w;
        float4 wv = *(const float4*)(W + (size_t)(k0 + wr) * N + col0 + wc);
        *(float4*)&Ws[wr][wc] = wv;
        __syncthreads();
#pragma unroll
        for (int kk = 0; kk < 8; kk++) {
            float a[8], w[8];
            *(float4*)(a)     = *(const float4*)&As[kk][ty << 3];
            *(float4*)(a + 4) = *(const float4*)&As[kk][(ty << 3) + 4];
            *(float4*)(w)     = *(const float4*)&Ws[kk][tx << 3];
            *(float4*)(w + 4) = *(const float4*)&Ws[kk][(tx << 3) + 4];
#pragma unroll
            for (int i = 0; i < 8; i++)
#pragma unroll
                for (int j = 0; j < 8; j++) acc[i][j] = fmaf(a[i], w[j], acc[i][j]);
        }
        __syncthreads();
    }
#pragma unroll
    for (int i = 0; i < 8; i++) {
        int r = row0 + (ty << 3) + i;
#pragma unroll
        for (int j = 0; j < 8; j++) {
            int c = col0 + (tx << 3) + j;
            float v = acc[i][j];
            if (bias) v += bias[c];
            if (EPI == 1) v += res[(size_t)r * N + c];
            else if (EPI == 2) v = gelu_f(v);
            C[(size_t)r * N + c] = v;
        }
    }
}

// ---------------- layernorm over D=384 ----------------
__global__ void __launch_bounds__(128) ln_kernel(const float* __restrict__ in,
                                                 float* __restrict__ out,
                                                 const float* __restrict__ gg,
                                                 const float* __restrict__ bb) {
    int row = blockIdx.x;
    int tid = threadIdx.x;
    const float* p = in + (size_t)row * 384;
    float v0 = p[tid], v1 = p[tid + 128], v2 = p[tid + 256];
    __shared__ float sh[128];
    sh[tid] = v0 + v1 + v2;
    __syncthreads();
    for (int o = 64; o; o >>= 1) { if (tid < o) sh[tid] += sh[tid + o]; __syncthreads(); }
    float mean = sh[0] * (1.0f / 384.0f);
    __syncthreads();
    float d0 = v0 - mean, d1 = v1 - mean, d2 = v2 - mean;
    sh[tid] = d0 * d0 + d1 * d1 + d2 * d2;
    __syncthreads();
    for (int o = 64; o; o >>= 1) { if (tid < o) sh[tid] += sh[tid + o]; __syncthreads(); }
    float rstd = rsqrtf(sh[0] * (1.0f / 384.0f) + 1e-5f);
    float* q = out + (size_t)row * 384;
    q[tid]       = d0 * rstd * gg[tid]       + bb[tid];
    q[tid + 128] = d1 * rstd * gg[tid + 128] + bb[tid + 128];
    q[tid + 256] = d2 * rstd * gg[tid + 256] + bb[tid + 256];
}

// ---------------- pos embed: gelu(center@pw1+pb1)@pw2+pb2 ----------------
__global__ void __launch_bounds__(128) pos_kernel(const float* __restrict__ ctr,
                                                  const float* __restrict__ pw1,
                                                  const float* __restrict__ pb1,
                                                  const float* __restrict__ pw2,
                                                  const float* __restrict__ pb2,
                                                  float* __restrict__ pos) {
    int row = blockIdx.x;
    int tid = threadIdx.x;
    float cx = ctr[row * 3], cy = ctr[row * 3 + 1], cz = ctr[row * 3 + 2];
    __shared__ float t[128];
    float u = cx * pw1[tid] + cy * pw1[128 + tid] + cz * pw1[256 + tid] + pb1[tid];
    t[tid] = gelu_f(u);
    __syncthreads();
    for (int j = tid; j < 384; j += 128) {
        float s = pb2[j];
#pragma unroll 8
        for (int k = 0; k < 128; k++) s = fmaf(t[k], pw2[k * 384 + j], s);
        pos[(size_t)row * 384 + j] = s;
    }
}

// ---------------- attention: S = scale * Q K^T ----------------
__global__ void __launch_bounds__(256) attn_qk_kernel(const float* __restrict__ qkv,
                                                      float* __restrict__ S) {
    int z = blockIdx.z;
    int b = z / NH, h = z - b * NH;
    const float* Qb = qkv + ((size_t)b * NG) * 1152 + h * 64;
    const float* Kb = Qb + 384;
    int m0 = blockIdx.y * 64, n0 = blockIdx.x * 64;
    __shared__ float Qs[16][65], Ks[16][65];
    int tid = threadIdx.x, tx = tid & 15, ty = tid >> 4;
    int lr = tid >> 2, lc = (tid & 3) * 4;
    float acc[4][4];
#pragma unroll
    for (int i = 0; i < 4; i++)
#pragma unroll
        for (int j = 0; j < 4; j++) acc[i][j] = 0.f;
    for (int d0 = 0; d0 < 64; d0 += 16) {
        float4 qv = *(const float4*)&Qb[(size_t)(m0 + lr) * 1152 + d0 + lc];
        float4 kv = *(const float4*)&Kb[(size_t)(n0 + lr) * 1152 + d0 + lc];
        Qs[lc + 0][lr] = qv.x; Qs[lc + 1][lr] = qv.y; Qs[lc + 2][lr] = qv.z; Qs[lc + 3][lr] = qv.w;
        Ks[lc + 0][lr] = kv.x; Ks[lc + 1][lr] = kv.y; Ks[lc + 2][lr] = kv.z; Ks[lc + 3][lr] = kv.w;
        __syncthreads();
#pragma unroll
        for (int kk = 0; kk < 16; kk++) {
            float a[4], w[4];
#pragma unroll
            for (int i = 0; i < 4; i++) a[i] = Qs[kk][ty * 4 + i];
#pragma unroll
            for (int j = 0; j < 4; j++) w[j] = Ks[kk][tx * 4 + j];
#pragma unroll
            for (int i = 0; i < 4; i++)
#pragma unroll
                for (int j = 0; j < 4; j++) acc[i][j] = fmaf(a[i], w[j], acc[i][j]);
        }
        __syncthreads();
    }
    float* out = S + (size_t)z * 512 * 512;
#pragma unroll
    for (int i = 0; i < 4; i++)
#pragma unroll
        for (int j = 0; j < 4; j++)
            out[(size_t)(m0 + ty * 4 + i) * 512 + n0 + tx * 4 + j] = acc[i][j] * 0.125f;
}

__global__ void __launch_bounds__(128) softmax_kernel(float* __restrict__ S) {
    size_t row = blockIdx.x;
    float* p = S + row * 512;
    int tid = threadIdx.x;
    float v[4];
#pragma unroll
    for (int u = 0; u < 4; u++) v[u] = p[tid + u * 128];
    float m = fmaxf(fmaxf(v[0], v[1]), fmaxf(v[2], v[3]));
    __shared__ float sh[128];
    sh[tid] = m;
    __syncthreads();
    for (int o = 64; o; o >>= 1) { if (tid < o) sh[tid] = fmaxf(sh[tid], sh[tid + o]); __syncthreads(); }
    m = sh[0];
    __syncthreads();
    float s = 0.f;
#pragma unroll
    for (int u = 0; u < 4; u++) { v[u] = expf(v[u] - m); s += v[u]; }
    sh[tid] = s;
    __syncthreads();
    for (int o = 64; o; o >>= 1) { if (tid < o) sh[tid] += sh[tid + o]; __syncthreads(); }
    float inv = 1.0f / sh[0];
#pragma unroll
    for (int u = 0; u < 4; u++) p[tid + u * 128] = v[u] * inv;
}

// ---------------- attention: O = A V ----------------
__global__ void __launch_bounds__(256) attn_av_kernel(const float* __restrict__ S,
                                                      const float* __restrict__ qkv,
                                                      float* __restrict__ O) {
    int z = blockIdx.y;
    int b = z / NH, h = z - b * NH;
    const float* A = S + (size_t)z * 512 * 512;
    const float* Vb = qkv + ((size_t)b * NG) * 1152 + 768 + h * 64;
    int m0 = blockIdx.x * 64;
    __shared__ float As[16][65], Vs[16][64];
    int tid = threadIdx.x, tx = tid & 15, ty = tid >> 4;
    int lr = tid >> 2, lc = (tid & 3) * 4;
    int vr = tid >> 4, vc = (tid & 15) * 4;
    float acc[4][4];
#pragma unroll
    for (int i = 0; i < 4; i++)
#pragma unroll
        for (int j = 0; j < 4; j++) acc[i][j] = 0.f;
    for (int n0 = 0; n0 < 512; n0 += 16) {
        float4 avv = *(const float4*)&A[(size_t)(m0 + lr) * 512 + n0 + lc];
        As[lc + 0][lr] = avv.x; As[lc + 1][lr] = avv.y; As[lc + 2][lr] = avv.z; As[lc + 3][lr] = avv.w;
        float4 vv = *(const float4*)&Vb[(size_t)(n0 + vr) * 1152 + vc];
        *(float4*)&Vs[vr][vc] = vv;
        __syncthreads();
#pragma unroll
        for (int kk = 0; kk < 16; kk++) {
            float a[4], w[4];
#pragma unroll
            for (int i = 0; i < 4; i++) a[i] = As[kk][ty * 4 + i];
#pragma unroll
            for (int j = 0; j < 4; j++) w[j] = Vs[kk][tx * 4 + j];
#pragma unroll
            for (int i = 0; i < 4; i++)
#pragma unroll
                for (int j = 0; j < 4; j++) acc[i][j] = fmaf(a[i], w[j], acc[i][j]);
        }
        __syncthreads();
    }
    float* Ob = O + ((size_t)b * NG) * 384 + h * 64;
#pragma unroll
    for (int i = 0; i < 4; i++)
#pragma unroll
        for (int j = 0; j < 4; j++)
            Ob[(size_t)(m0 + ty * 4 + i) * 384 + tx * 4 + j] = acc[i][j];
}

// ---------------- host ----------------
extern "C" void kernel_launch(void* const* d_in, const int* in_sizes, int n_in,
                              void* d_out, int out_size) {
    const float* pts   = (const float*)d_in[0];
    const float* w1    = (const float*)d_in[1];
    const float* b1    = (const float*)d_in[2];
    const float* bn1g  = (const float*)d_in[3];
    const float* bn1b  = (const float*)d_in[4];
    const float* w2    = (const float*)d_in[5];
    const float* b2    = (const float*)d_in[6];
    const float* w3    = (const float*)d_in[7];
    const float* b3    = (const float*)d_in[8];
    const float* bn2g  = (const float*)d_in[9];
    const float* bn2b  = (const float*)d_in[10];
    const float* w4    = (const float*)d_in[11];
    const float* b4    = (const float*)d_in[12];
    const float* pw1   = (const float*)d_in[13];
    const float* pb1   = (const float*)d_in[14];
    const float* pw2   = (const float*)d_in[15];
    const float* pb2   = (const float*)d_in[16];
    const float* ln1g  = (const float*)d_in[17];
    const float* ln1b  = (const float*)d_in[18];
    const float* qkvw  = (const float*)d_in[19];
    const float* projw = (const float*)d_in[20];
    const float* projb = (const float*)d_in[21];
    const float* ln2g  = (const float*)d_in[22];
    const float* ln2b  = (const float*)d_in[23];
    const float* fc1w  = (const float*)d_in[24];
    const float* fc1b  = (const float*)d_in[25];
    const float* fc2w  = (const float*)d_in[26];
    const float* fc2b  = (const float*)d_in[27];
    const float* nfg   = (const float*)d_in[28];
    const float* nfb   = (const float*)d_in[29];

    static float* S = nullptr;
    if (!S) cudaGetSymbolAddress((void**)&S, g_scratch);

    float* h1   = S + O_H1;
    float* f    = S + O_F;
    float* h3   = S + O_H3;
    float* f4   = S + O_F4;
    float* fg   = S + O_FG;
    float* x    = S + O_X;
    float* xin  = S + O_XIN;
    float* hln  = S + O_HLN;
    float* ob   = S + O_OB;
    float* pos  = S + O_POS;
    float* qkv  = S + O_QKV;
    float* sc   = S + O_SC;
    float* ff   = S + O_FF;
    float* ctr  = S + O_CTR;
    float* st   = S + O_ST;
    float* s1a = st, *s2a = st + 128, *s1b = st + 256, *s2b = st + 768;
    float* scale1 = st + 1280, *shift1 = st + 1408;
    float* scale2 = st + 1536, *shift2 = st + 2048;

    float* out     = (float*)d_out;
    float* out_x   = out;                              // [16,512,384]
    float* out_nbr = out + (size_t)BGc * 384;          // [16,512,32,3]
    float* out_ctr = out_nbr + (size_t)BGc * NK * 3;   // [16,512,3]

    // stats must be zeroed every launch (graph replays reuse scratch)
    zero_kernel<<<16, 256>>>(st, 4096);

    fps_kernel<<<NB, 1024>>>(pts, ctr, out_ctr);
    knn_kernel<<<BGc, 256>>>(pts, ctr, out_nbr);

    enc1_kernel<<<(M1 * 128) / 256, 256>>>(out_nbr, w1, b1, h1);
    bnstats_kernel<<<M1 / 512, 128>>>(h1, 128, s1a, s2a);
    bnfin_kernel<<<1, 128>>>(s1a, s2a, 1.0f / (float)M1, bn1g, bn1b, scale1, shift1);
    gemm128_kernel<1, 0><<<dim3(2, 2048), 256>>>(h1, w2, b2, nullptr, f, M1, 256, 128, scale1, shift1);
    maxk_kernel<<<(BGc * 256) / 256, 256>>>(f, fg, 256, BGc * 256);
    gemm128_kernel<2, 0><<<dim3(4, 2048), 256>>>(f, w3, b3, nullptr, h3, M1, 512, 512, fg, nullptr);
    bnstats_kernel<<<M1 / 512, 512>>>(h3, 512, s1b, s2b);
    bnfin_kernel<<<1, 512>>>(s1b, s2b, 1.0f / (float)M1, bn2g, bn2b, scale2, shift2);
    gemm128_kernel<1, 0><<<dim3(3, 2048), 256>>>(h3, w4, b4, nullptr, f4, M1, 384, 512, scale2, shift2);
    maxk_kernel<<<(BGc * 384) / 256, 256>>>(f4, x, 384, BGc * 384);

    pos_kernel<<<BGc, 128>>>(ctr, pw1, pb1, pw2, pb2, pos);

    for (int l = 0; l < NL; l++) {
        add_kernel<<<(BGc * 384) / 256, 256>>>(x, pos, xin, BGc * 384);
        ln_kernel<<<BGc, 128>>>(xin, hln, ln1g + l * 384, ln1b + l * 384);
        gemm128_kernel<0, 0><<<dim3(9, 64), 256>>>(hln, qkvw + (size_t)l * 384 * 1152,
                                                   nullptr, nullptr, qkv, BGc, 1152, 384,
                                                   nullptr, nullptr);
        attn_qk_kernel<<<dim3(8, 8, NB * NH), 256>>>(qkv, sc);
        softmax_kernel<<<NB * NH * 512, 128>>>(sc);
        attn_av_kernel<<<dim3(8, NB * NH), 256>>>(sc, qkv, ob);
        gemm128_kernel<0, 1><<<dim3(3, 64), 256>>>(ob, projw + (size_t)l * 384 * 384,
                                                   projb + l * 384, xin, x, BGc, 384, 384,
                                                   nullptr, nullptr);
        ln_kernel<<<BGc, 128>>>(x, hln, ln2g + l * 384, ln2b + l * 384);
        gemm128_kernel<0, 2><<<dim3(12, 64), 256>>>(hln, fc1w + (size_t)l * 384 * 1536,
                                                    fc1b + l * 1536, nullptr, ff, BGc, 1536, 384,
                                                    nullptr, nullptr);
        gemm128_kernel<0, 1><<<dim3(3, 64), 256>>>(ff, fc2w + (size_t)l * 1536 * 384,
                                                   fc2b + l * 384, x, x, BGc, 384, 1536,
                                                   nullptr, nullptr);
    }
    ln_kernel<<<BGc, 128>>>(x, out_x, nfg, nfb);
}

// round 4
// speedup vs baseline: 1.1434x; 1.1434x over previous
#include <cuda_runtime.h>
#include <math.h>
#include <stdint.h>

// Problem dims
#define NB 16
#define NP 8192
#define NG 512
#define NK 32
#define ND 384
#define NL 12
#define NH 6
#define BGc (NB*NG)      /* 8192 */
#define M1  (BGc*NK)     /* 262144 */

// ---------------- scratch layout ----------------
constexpr size_t O_H1  = 0;
constexpr size_t O_F   = O_H1  + (size_t)M1*128;
constexpr size_t O_H3  = O_F   + (size_t)M1*256;
constexpr size_t O_F4  = O_H3  + (size_t)M1*512;
constexpr size_t O_FG  = O_F4  + (size_t)M1*384;
constexpr size_t O_X   = O_FG  + (size_t)BGc*256;
constexpr size_t O_XIN = O_X   + (size_t)BGc*384;
constexpr size_t O_HLN = O_XIN + (size_t)BGc*384;
constexpr size_t O_OB  = O_HLN + (size_t)BGc*384;
constexpr size_t O_POS = O_OB  + (size_t)BGc*384;
constexpr size_t O_QKV = O_POS + (size_t)BGc*384;
constexpr size_t O_SC  = O_QKV + (size_t)BGc*1152;
constexpr size_t O_FF  = O_SC  + (size_t)96*512*512;
constexpr size_t O_CTR = O_FF  + (size_t)BGc*1536;
constexpr size_t O_ST  = O_CTR + (size_t)BGc*3;
constexpr size_t SCRATCH_TOTAL = O_ST + 4096;

__device__ float g_scratch[SCRATCH_TOTAL];

__device__ __forceinline__ float gelu_f(float x) {
    return 0.5f * x * (1.0f + erff(x * 0.70710678118654752f));
}

// ---------------- tf32 helpers (baseline PTX, sm_80+) ----------------
__device__ __forceinline__ void tf32_split(float x, uint32_t& hi, uint32_t& lo) {
    uint32_t h;
    asm("cvt.rna.tf32.f32 %0, %1;" : "=r"(h) : "f"(x));
    float l = x - __uint_as_float(h);
    uint32_t lw;
    asm("cvt.rna.tf32.f32 %0, %1;" : "=r"(lw) : "f"(l));
    hi = h; lo = lw;
}

__device__ __forceinline__ void mma_tf32(float* d, const uint32_t* a, const uint32_t* b) {
    asm volatile(
        "mma.sync.aligned.m16n8k8.row.col.f32.tf32.tf32.f32 "
        "{%0,%1,%2,%3}, {%4,%5,%6,%7}, {%8,%9}, {%0,%1,%2,%3};"
        : "+f"(d[0]), "+f"(d[1]), "+f"(d[2]), "+f"(d[3])
        : "r"(a[0]), "r"(a[1]), "r"(a[2]), "r"(a[3]), "r"(b[0]), "r"(b[1]));
}

// ============ TF32x3 mma.sync GEMM: 128x128 block tile, K in 32-chunks ============
// 8 warps: 4 warp-rows x 2 warp-cols; warp tile 32x64 (2 m16 x 8 n8 mma tiles)
// AMODE 0: plain A[M,K]; 1: relu(A*q0[k]+q1[k]); 2: concat(fg=q0[row/32], f=A[row]) K=512
// EPI   0: +bias; 1: +bias+res; 2: gelu(+bias)
#define AS_STRIDE 33
#define BS_STRIDE 136
static constexpr int GE_SMEM = (2 * 128 * AS_STRIDE + 2 * 32 * BS_STRIDE) * 4;  // 68608 B

template <int AMODE, int EPI>
__global__ void __launch_bounds__(256) mmagemm_kernel(
    const float* __restrict__ A, const float* __restrict__ W,
    const float* __restrict__ bias, const float* __restrict__ res,
    float* __restrict__ C, int M, int N, int K,
    const float* __restrict__ q0, const float* __restrict__ q1) {
    extern __shared__ float sm[];
    float* Ahi = sm;
    float* Alo = Ahi + 128 * AS_STRIDE;
    float* Bhi = Alo + 128 * AS_STRIDE;
    float* Blo = Bhi + 32 * BS_STRIDE;

    const int tid = threadIdx.x;
    const int warp = tid >> 5, lane = tid & 31;
    const int row0 = blockIdx.y << 7, col0 = blockIdx.x << 7;
    const int wr = (warp & 3) << 5;    // warp row base (0/32/64/96)
    const int wc = (warp >> 2) << 6;   // warp col base (0/64)

    float d[2][8][4];
#pragma unroll
    for (int mt = 0; mt < 2; mt++)
#pragma unroll
        for (int nt = 0; nt < 8; nt++)
#pragma unroll
            for (int i = 0; i < 4; i++) d[mt][nt][i] = 0.f;

    const int arow = tid >> 1;
    const int akoff = (tid & 1) << 4;
    const int grow = row0 + arow;
    const int bn = tid & 127;
    const int bkoff = (tid >> 7) << 4;

    const int lg = lane >> 2;   // group id
    const int lt = lane & 3;    // thread in group

    const int nblk = K >> 5;
    for (int kb = 0; kb < nblk; kb++) {
        const int kbase = kb << 5;
        // ---- stage A chunk (128 x 32): thread = (row, 16-k half) ----
        {
            float v[16];
            const int kg = kbase + akoff;
            if (AMODE == 2) {
                const float* src = (kg < 256)
                    ? (q0 + ((size_t)(grow >> 5)) * 256 + kg)
                    : (A + ((size_t)grow) * 256 + (kg - 256));
#pragma unroll
                for (int i = 0; i < 4; i++) *(float4*)&v[i * 4] = *(const float4*)&src[i * 4];
            } else {
                const float* src = A + (size_t)grow * K + kg;
#pragma unroll
                for (int i = 0; i < 4; i++) *(float4*)&v[i * 4] = *(const float4*)&src[i * 4];
                if (AMODE == 1) {
#pragma unroll
                    for (int c = 0; c < 16; c++)
                        v[c] = fmaxf(fmaf(v[c], q0[kg + c], q1[kg + c]), 0.f);
                }
            }
#pragma unroll
            for (int i = 0; i < 16; i++) {
                uint32_t h, l;
                tf32_split(v[i], h, l);
                Ahi[arow * AS_STRIDE + akoff + i] = __uint_as_float(h);
                Alo[arow * AS_STRIDE + akoff + i] = __uint_as_float(l);
            }
        }
        // ---- stage B chunk (32 x 128): thread = (n col, 16-k half) ----
        {
            const float* wp = W + (size_t)(kbase + bkoff) * N + col0 + bn;
#pragma unroll
            for (int i = 0; i < 16; i++) {
                uint32_t h, l;
                tf32_split(wp[(size_t)i * N], h, l);
                Bhi[(bkoff + i) * BS_STRIDE + bn] = __uint_as_float(h);
                Blo[(bkoff + i) * BS_STRIDE + bn] = __uint_as_float(l);
            }
        }
        __syncthreads();
#pragma unroll
        for (int k8 = 0; k8 < 32; k8 += 8) {
            uint32_t ah[2][4], al[2][4];
#pragma unroll
            for (int mt = 0; mt < 2; mt++) {
                const int rr = wr + mt * 16 + lg;
                const int cc = k8 + lt;
                ah[mt][0] = __float_as_uint(Ahi[rr * AS_STRIDE + cc]);
                ah[mt][1] = __float_as_uint(Ahi[(rr + 8) * AS_STRIDE + cc]);
                ah[mt][2] = __float_as_uint(Ahi[rr * AS_STRIDE + cc + 4]);
                ah[mt][3] = __float_as_uint(Ahi[(rr + 8) * AS_STRIDE + cc + 4]);
                al[mt][0] = __float_as_uint(Alo[rr * AS_STRIDE + cc]);
                al[mt][1] = __float_as_uint(Alo[(rr + 8) * AS_STRIDE + cc]);
                al[mt][2] = __float_as_uint(Alo[rr * AS_STRIDE + cc + 4]);
                al[mt][3] = __float_as_uint(Alo[(rr + 8) * AS_STRIDE + cc + 4]);
            }
            uint32_t bh[8][2], bl[8][2];
#pragma unroll
            for (int nt = 0; nt < 8; nt++) {
                const int kk = k8 + lt;
                const int nn = wc + nt * 8 + lg;
                bh[nt][0] = __float_as_uint(Bhi[kk * BS_STRIDE + nn]);
                bh[nt][1] = __float_as_uint(Bhi[(kk + 4) * BS_STRIDE + nn]);
                bl[nt][0] = __float_as_uint(Blo[kk * BS_STRIDE + nn]);
                bl[nt][1] = __float_as_uint(Blo[(kk + 4) * BS_STRIDE + nn]);
            }
#pragma unroll
            for (int mt = 0; mt < 2; mt++)
#pragma unroll
                for (int nt = 0; nt < 8; nt++) {
                    mma_tf32(d[mt][nt], ah[mt], bh[nt]);
                    mma_tf32(d[mt][nt], al[mt], bh[nt]);
                    mma_tf32(d[mt][nt], ah[mt], bl[nt]);
                }
        }
        __syncthreads();
    }

    // ---- epilogue ----
#pragma unroll
    for (int mt = 0; mt < 2; mt++) {
        const int r1 = row0 + wr + mt * 16 + lg;
        const int r2 = r1 + 8;
#pragma unroll
        for (int nt = 0; nt < 8; nt++) {
            const int c = col0 + wc + nt * 8 + lt * 2;
            float v0 = d[mt][nt][0], v1 = d[mt][nt][1];
            float v2 = d[mt][nt][2], v3 = d[mt][nt][3];
            if (bias) {
                float b0 = bias[c], b1 = bias[c + 1];
                v0 += b0; v1 += b1; v2 += b0; v3 += b1;
            }
            if (EPI == 1) {
                v0 += res[(size_t)r1 * N + c];
                v1 += res[(size_t)r1 * N + c + 1];
                v2 += res[(size_t)r2 * N + c];
                v3 += res[(size_t)r2 * N + c + 1];
            } else if (EPI == 2) {
                v0 = gelu_f(v0); v1 = gelu_f(v1); v2 = gelu_f(v2); v3 = gelu_f(v3);
            }
            C[(size_t)r1 * N + c]     = v0;
            C[(size_t)r1 * N + c + 1] = v1;
            C[(size_t)r2 * N + c]     = v2;
            C[(size_t)r2 * N + c + 1] = v3;
        }
    }
}

// ---------------- zero / add / maxk ----------------
__global__ void zero_kernel(float* p, int n) {
    int i = blockIdx.x * blockDim.x + threadIdx.x;
    if (i < n) p[i] = 0.0f;
}

__global__ void add_kernel(const float* __restrict__ a, const float* __restrict__ b,
                           float* __restrict__ c, int n) {
    int i = blockIdx.x * blockDim.x + threadIdx.x;
    if (i < n) c[i] = a[i] + b[i];
}

__global__ void maxk_kernel(const float* __restrict__ in, float* __restrict__ out,
                            int C, int total) {
    int idx = blockIdx.x * blockDim.x + threadIdx.x;
    if (idx >= total) return;
    int r = idx / C, c = idx - r * C;
    const float* p = in + ((size_t)r * 32) * C + c;
    float m = p[0];
#pragma unroll
    for (int t = 1; t < 32; t++) m = fmaxf(m, p[(size_t)t * C]);
    out[idx] = m;
}

// ---------------- FPS (warp-shuffle argmax reduction) ----------------
__global__ void __launch_bounds__(1024) fps_kernel(const float* __restrict__ pts,
                                                   float* __restrict__ ctr,
                                                   float* __restrict__ ctr_out) {
    int b = blockIdx.x;
    int tid = threadIdx.x, wid = tid >> 5, lane = tid & 31;
    const float* P = pts + (size_t)b * NP * 3;
    float px[8], py[8], pz[8], dl[8];
#pragma unroll
    for (int t = 0; t < 8; t++) {
        int j = tid + t * 1024;
        px[t] = P[j * 3 + 0]; py[t] = P[j * 3 + 1]; pz[t] = P[j * 3 + 2];
        dl[t] = 1e10f;
    }
    __shared__ float lastp[3];
    __shared__ float wv_s[32];
    __shared__ int   wi_s[32];
    if (tid == 0) {
        lastp[0] = P[0]; lastp[1] = P[1]; lastp[2] = P[2];
        size_t co = (size_t)b * NG * 3;
        ctr[co] = P[0]; ctr[co + 1] = P[1]; ctr[co + 2] = P[2];
        ctr_out[co] = P[0]; ctr_out[co + 1] = P[1]; ctr_out[co + 2] = P[2];
    }
    __syncthreads();
    for (int s = 1; s < NG; s++) {
        float lx = lastp[0], ly = lastp[1], lz = lastp[2];
        float bv = -1.0f; int bi = 0;
#pragma unroll
        for (int t = 0; t < 8; t++) {
            float dx = __fsub_rn(px[t], lx);
            float dy = __fsub_rn(py[t], ly);
            float dz = __fsub_rn(pz[t], lz);
            float d = __fadd_rn(__fadd_rn(__fmul_rn(dx, dx), __fmul_rn(dy, dy)),
                                __fmul_rn(dz, dz));
            float nd = fminf(dl[t], d);
            dl[t] = nd;
            if (nd > bv) { bv = nd; bi = tid + t * 1024; }
        }
#pragma unroll
        for (int o = 16; o; o >>= 1) {
            float v2 = __shfl_xor_sync(0xFFFFFFFFu, bv, o);
            int   i2 = __shfl_xor_sync(0xFFFFFFFFu, bi, o);
            if (v2 > bv || (v2 == bv && i2 < bi)) { bv = v2; bi = i2; }
        }
        if (lane == 0) { wv_s[wid] = bv; wi_s[wid] = bi; }
        __syncthreads();
        if (wid == 0) {
            bv = wv_s[lane]; bi = wi_s[lane];
#pragma unroll
            for (int o = 16; o; o >>= 1) {
                float v2 = __shfl_xor_sync(0xFFFFFFFFu, bv, o);
                int   i2 = __shfl_xor_sync(0xFFFFFFFFu, bi, o);
                if (v2 > bv || (v2 == bv && i2 < bi)) { bv = v2; bi = i2; }
            }
            if (lane == 0) {
                float qx = P[bi * 3], qy = P[bi * 3 + 1], qz = P[bi * 3 + 2];
                lastp[0] = qx; lastp[1] = qy; lastp[2] = qz;
                size_t co = ((size_t)b * NG + s) * 3;
                ctr[co] = qx; ctr[co + 1] = qy; ctr[co + 2] = qz;
                ctr_out[co] = qx; ctr_out[co + 1] = qy; ctr_out[co + 2] = qz;
            }
        }
        __syncthreads();
    }
}

// ---------------- KNN (bit-exact d2 vs reference) ----------------
__global__ void __launch_bounds__(256) knn_kernel(const float* __restrict__ pts,
                                                  const float* __restrict__ ctr,
                                                  float* __restrict__ nbr_out) {
    int bg = blockIdx.x;
    int b = bg >> 9;
    const float* P = pts + (size_t)b * NP * 3;
    float cx = ctr[bg * 3 + 0], cy = ctr[bg * 3 + 1], cz = ctr[bg * 3 + 2];
    float c2 = __fadd_rn(__fadd_rn(__fmul_rn(cx, cx), __fmul_rn(cy, cy)), __fmul_rn(cz, cz));
    __shared__ float d2s[NP];
    int tid = threadIdx.x;
    for (int j = tid; j < NP; j += 256) {
        float px = P[j * 3], py = P[j * 3 + 1], pz = P[j * 3 + 2];
        float p2 = __fadd_rn(__fadd_rn(__fmul_rn(px, px), __fmul_rn(py, py)), __fmul_rn(pz, pz));
        float dot = __fmaf_rn(cz, pz, __fmaf_rn(cy, py, __fmul_rn(cx, px)));
        d2s[j] = __fsub_rn(__fadd_rn(c2, p2), __fmul_rn(2.0f, dot));
    }
    __syncthreads();
    __shared__ float rv[256];
    __shared__ int ri[256];
    __shared__ int chosen[NK];
    for (int sel = 0; sel < NK; sel++) {
        float bv = 3.4e38f; int bi = 0x7fffffff;
        for (int j = tid; j < NP; j += 256) {
            float v = d2s[j];
            if (v < bv) { bv = v; bi = j; }
        }
        rv[tid] = bv; ri[tid] = bi;
        __syncthreads();
        for (int o = 128; o; o >>= 1) {
            if (tid < o) {
                float v2 = rv[tid + o]; int i2 = ri[tid + o];
                if (v2 < rv[tid] || (v2 == rv[tid] && i2 < ri[tid])) {
                    rv[tid] = v2; ri[tid] = i2;
                }
            }
            __syncthreads();
        }
        if (tid == 0) { chosen[sel] = ri[0]; d2s[ri[0]] = 3.4e38f; }
        __syncthreads();
    }
    if (tid < NK) {
        int j = chosen[tid];
        size_t o = ((size_t)bg * NK + tid) * 3;
        nbr_out[o + 0] = P[j * 3 + 0] - cx;
        nbr_out[o + 1] = P[j * 3 + 1] - cy;
        nbr_out[o + 2] = P[j * 3 + 2] - cz;
    }
}

// ---------------- encoder first linear 3->128 ----------------
__global__ void enc1_kernel(const float* __restrict__ nbr, const float* __restrict__ w1,
                            const float* __restrict__ b1, float* __restrict__ h1) {
    size_t idx = (size_t)blockIdx.x * blockDim.x + threadIdx.x;
    if (idx >= (size_t)M1 * 128) return;
    size_t i = idx >> 7;
    int c = (int)(idx & 127);
    float x0 = nbr[i * 3], x1 = nbr[i * 3 + 1], x2 = nbr[i * 3 + 2];
    h1[idx] = x0 * w1[c] + x1 * w1[128 + c] + x2 * w1[256 + c] + b1[c];
}

// ---------------- BN stats ----------------
__global__ void bnstats_kernel(const float* __restrict__ h, int C,
                               float* __restrict__ s1, float* __restrict__ s2) {
    int c = threadIdx.x;
    size_t r0 = (size_t)blockIdx.x * 512;
    const float* p = h + r0 * C + c;
    float a = 0.f, q = 0.f;
    for (int r = 0; r < 512; r++) {
        float v = p[(size_t)r * C];
        a += v; q += v * v;
    }
    atomicAdd(&s1[c], a);
    atomicAdd(&s2[c], q);
}

__global__ void bnfin_kernel(const float* __restrict__ s1, const float* __restrict__ s2,
                             float invM, const float* __restrict__ g, const float* __restrict__ b,
                             float* __restrict__ scale, float* __restrict__ shift) {
    int c = threadIdx.x;
    float mean = s1[c] * invM;
    float var = s2[c] * invM - mean * mean;
    float r = rsqrtf(var + 1e-5f);
    float sc = g[c] * r;
    scale[c] = sc;
    shift[c] = b[c] - mean * sc;
}

// ---------------- layernorm over D=384 ----------------
__global__ void __launch_bounds__(128) ln_kernel(const float* __restrict__ in,
                                                 float* __restrict__ out,
                                                 const float* __restrict__ gg,
                                                 const float* __restrict__ bb) {
    int row = blockIdx.x;
    int tid = threadIdx.x;
    const float* p = in + (size_t)row * 384;
    float v0 = p[tid], v1 = p[tid + 128], v2 = p[tid + 256];
    __shared__ float sh[128];
    sh[tid] = v0 + v1 + v2;
    __syncthreads();
    for (int o = 64; o; o >>= 1) { if (tid < o) sh[tid] += sh[tid + o]; __syncthreads(); }
    float mean = sh[0] * (1.0f / 384.0f);
    __syncthreads();
    float d0 = v0 - mean, d1 = v1 - mean, d2 = v2 - mean;
    sh[tid] = d0 * d0 + d1 * d1 + d2 * d2;
    __syncthreads();
    for (int o = 64; o; o >>= 1) { if (tid < o) sh[tid] += sh[tid + o]; __syncthreads(); }
    float rstd = rsqrtf(sh[0] * (1.0f / 384.0f) + 1e-5f);
    float* q = out + (size_t)row * 384;
    q[tid]       = d0 * rstd * gg[tid]       + bb[tid];
    q[tid + 128] = d1 * rstd * gg[tid + 128] + bb[tid + 128];
    q[tid + 256] = d2 * rstd * gg[tid + 256] + bb[tid + 256];
}

// ---------------- pos embed ----------------
__global__ void __launch_bounds__(128) pos_kernel(const float* __restrict__ ctr,
                                                  const float* __restrict__ pw1,
                                                  const float* __restrict__ pb1,
                                                  const float* __restrict__ pw2,
                                                  const float* __restrict__ pb2,
                                                  float* __restrict__ pos) {
    int row = blockIdx.x;
    int tid = threadIdx.x;
    float cx = ctr[row * 3], cy = ctr[row * 3 + 1], cz = ctr[row * 3 + 2];
    __shared__ float t[128];
    float u = cx * pw1[tid] + cy * pw1[128 + tid] + cz * pw1[256 + tid] + pb1[tid];
    t[tid] = gelu_f(u);
    __syncthreads();
    for (int j = tid; j < 384; j += 128) {
        float s = pb2[j];
#pragma unroll 8
        for (int k = 0; k < 128; k++) s = fmaf(t[k], pw2[k * 384 + j], s);
        pos[(size_t)row * 384 + j] = s;
    }
}

// ---------------- attention: S = scale * Q K^T ----------------
__global__ void __launch_bounds__(256) attn_qk_kernel(const float* __restrict__ qkv,
                                                      float* __restrict__ S) {
    int z = blockIdx.z;
    int b = z / NH, h = z - b * NH;
    const float* Qb = qkv + ((size_t)b * NG) * 1152 + h * 64;
    const float* Kb = Qb + 384;
    int m0 = blockIdx.y * 64, n0 = blockIdx.x * 64;
    __shared__ float Qs[16][65], Ks[16][65];
    int tid = threadIdx.x, tx = tid & 15, ty = tid >> 4;
    int lr = tid >> 2, lc = (tid & 3) * 4;
    float acc[4][4];
#pragma unroll
    for (int i = 0; i < 4; i++)
#pragma unroll
        for (int j = 0; j < 4; j++) acc[i][j] = 0.f;
    for (int d0 = 0; d0 < 64; d0 += 16) {
        float4 qv = *(const float4*)&Qb[(size_t)(m0 + lr) * 1152 + d0 + lc];
        float4 kv = *(const float4*)&Kb[(size_t)(n0 + lr) * 1152 + d0 + lc];
        Qs[lc + 0][lr] = qv.x; Qs[lc + 1][lr] = qv.y; Qs[lc + 2][lr] = qv.z; Qs[lc + 3][lr] = qv.w;
        Ks[lc + 0][lr] = kv.x; Ks[lc + 1][lr] = kv.y; Ks[lc + 2][lr] = kv.z; Ks[lc + 3][lr] = kv.w;
        __syncthreads();
#pragma unroll
        for (int kk = 0; kk < 16; kk++) {
            float a[4], w[4];
#pragma unroll
            for (int i = 0; i < 4; i++) a[i] = Qs[kk][ty * 4 + i];
#pragma unroll
            for (int j = 0; j < 4; j++) w[j] = Ks[kk][tx * 4 + j];
#pragma unroll
            for (int i = 0; i < 4; i++)
#pragma unroll
                for (int j = 0; j < 4; j++) acc[i][j] = fmaf(a[i], w[j], acc[i][j]);
        }
        __syncthreads();
    }
    float* out = S + (size_t)z * 512 * 512;
#pragma unroll
    for (int i = 0; i < 4; i++)
#pragma unroll
        for (int j = 0; j < 4; j++)
            out[(size_t)(m0 + ty * 4 + i) * 512 + n0 + tx * 4 + j] = acc[i][j] * 0.125f;
}

__global__ void __launch_bounds__(128) softmax_kernel(float* __restrict__ S) {
    size_t row = blockIdx.x;
    float* p = S + row * 512;
    int tid = threadIdx.x;
    float v[4];
#pragma unroll
    for (int u = 0; u < 4; u++) v[u] = p[tid + u * 128];
    float m = fmaxf(fmaxf(v[0], v[1]), fmaxf(v[2], v[3]));
    __shared__ float sh[128];
    sh[tid] = m;
    __syncthreads();
    for (int o = 64; o; o >>= 1) { if (tid < o) sh[tid] = fmaxf(sh[tid], sh[tid + o]); __syncthreads(); }
    m = sh[0];
    __syncthreads();
    float s = 0.f;
#pragma unroll
    for (int u = 0; u < 4; u++) { v[u] = expf(v[u] - m); s += v[u]; }
    sh[tid] = s;
    __syncthreads();
    for (int o = 64; o; o >>= 1) { if (tid < o) sh[tid] += sh[tid + o]; __syncthreads(); }
    float inv = 1.0f / sh[0];
#pragma unroll
    for (int u = 0; u < 4; u++) p[tid + u * 128] = v[u] * inv;
}

// ---------------- attention: O = A V ----------------
__global__ void __launch_bounds__(256) attn_av_kernel(const float* __restrict__ S,
                                                      const float* __restrict__ qkv,
                                                      float* __restrict__ O) {
    int z = blockIdx.y;
    int b = z / NH, h = z - b * NH;
    const float* A = S + (size_t)z * 512 * 512;
    const float* Vb = qkv + ((size_t)b * NG) * 1152 + 768 + h * 64;
    int m0 = blockIdx.x * 64;
    __shared__ float As[16][65], Vs[16][64];
    int tid = threadIdx.x, tx = tid & 15, ty = tid >> 4;
    int lr = tid >> 2, lc = (tid & 3) * 4;
    int vr = tid >> 4, vc = (tid & 15) * 4;
    float acc[4][4];
#pragma unroll
    for (int i = 0; i < 4; i++)
#pragma unroll
        for (int j = 0; j < 4; j++) acc[i][j] = 0.f;
    for (int n0 = 0; n0 < 512; n0 += 16) {
        float4 avv = *(const float4*)&A[(size_t)(m0 + lr) * 512 + n0 + lc];
        As[lc + 0][lr] = avv.x; As[lc + 1][lr] = avv.y; As[lc + 2][lr] = avv.z; As[lc + 3][lr] = avv.w;
        float4 vv = *(const float4*)&Vb[(size_t)(n0 + vr) * 1152 + vc];
        *(float4*)&Vs[vr][vc] = vv;
        __syncthreads();
#pragma unroll
        for (int kk = 0; kk < 16; kk++) {
            float a[4], w[4];
#pragma unroll
            for (int i = 0; i < 4; i++) a[i] = As[kk][ty * 4 + i];
#pragma unroll
            for (int j = 0; j < 4; j++) w[j] = Vs[kk][tx * 4 + j];
#pragma unroll
            for (int i = 0; i < 4; i++)
#pragma unroll
                for (int j = 0; j < 4; j++) acc[i][j] = fmaf(a[i], w[j], acc[i][j]);
        }
        __syncthreads();
    }
    float* Ob = O + ((size_t)b * NG) * 384 + h * 64;
#pragma unroll
    for (int i = 0; i < 4; i++)
#pragma unroll
        for (int j = 0; j < 4; j++)
            Ob[(size_t)(m0 + ty * 4 + i) * 384 + tx * 4 + j] = acc[i][j];
}

// ---------------- host ----------------
extern "C" void kernel_launch(void* const* d_in, const int* in_sizes, int n_in,
                              void* d_out, int out_size) {
    const float* pts   = (const float*)d_in[0];
    const float* w1    = (const float*)d_in[1];
    const float* b1    = (const float*)d_in[2];
    const float* bn1g  = (const float*)d_in[3];
    const float* bn1b  = (const float*)d_in[4];
    const float* w2    = (const float*)d_in[5];
    const float* b2    = (const float*)d_in[6];
    const float* w3    = (const float*)d_in[7];
    const float* b3    = (const float*)d_in[8];
    const float* bn2g  = (const float*)d_in[9];
    const float* bn2b  = (const float*)d_in[10];
    const float* w4    = (const float*)d_in[11];
    const float* b4    = (const float*)d_in[12];
    const float* pw1   = (const float*)d_in[13];
    const float* pb1   = (const float*)d_in[14];
    const float* pw2   = (const float*)d_in[15];
    const float* pb2   = (const float*)d_in[16];
    const float* ln1g  = (const float*)d_in[17];
    const float* ln1b  = (const float*)d_in[18];
    const float* qkvw  = (const float*)d_in[19];
    const float* projw = (const float*)d_in[20];
    const float* projb = (const float*)d_in[21];
    const float* ln2g  = (const float*)d_in[22];
    const float* ln2b  = (const float*)d_in[23];
    const float* fc1w  = (const float*)d_in[24];
    const float* fc1b  = (const float*)d_in[25];
    const float* fc2w  = (const float*)d_in[26];
    const float* fc2b  = (const float*)d_in[27];
    const float* nfg   = (const float*)d_in[28];
    const float* nfb   = (const float*)d_in[29];

    static float* S = nullptr;
    if (!S) {
        cudaGetSymbolAddress((void**)&S, g_scratch);
        cudaFuncSetAttribute(mmagemm_kernel<0, 0>, cudaFuncAttributeMaxDynamicSharedMemorySize, GE_SMEM);
        cudaFuncSetAttribute(mmagemm_kernel<0, 1>, cudaFuncAttributeMaxDynamicSharedMemorySize, GE_SMEM);
        cudaFuncSetAttribute(mmagemm_kernel<0, 2>, cudaFuncAttributeMaxDynamicSharedMemorySize, GE_SMEM);
        cudaFuncSetAttribute(mmagemm_kernel<1, 0>, cudaFuncAttributeMaxDynamicSharedMemorySize, GE_SMEM);
        cudaFuncSetAttribute(mmagemm_kernel<2, 0>, cudaFuncAttributeMaxDynamicSharedMemorySize, GE_SMEM);
    }

    float* h1   = S + O_H1;
    float* f    = S + O_F;
    float* h3   = S + O_H3;
    float* f4   = S + O_F4;
    float* fg   = S + O_FG;
    float* x    = S + O_X;
    float* xin  = S + O_XIN;
    float* hln  = S + O_HLN;
    float* ob   = S + O_OB;
    float* pos  = S + O_POS;
    float* qkv  = S + O_QKV;
    float* sc   = S + O_SC;
    float* ff   = S + O_FF;
    float* ctr  = S + O_CTR;
    float* st   = S + O_ST;
    float* s1a = st, *s2a = st + 128, *s1b = st + 256, *s2b = st + 768;
    float* scale1 = st + 1280, *shift1 = st + 1408;
    float* scale2 = st + 1536, *shift2 = st + 2048;

    float* out     = (float*)d_out;
    float* out_x   = out;                              // [16,512,384]
    float* out_nbr = out + (size_t)BGc * 384;          // [16,512,32,3]
    float* out_ctr = out_nbr + (size_t)BGc * NK * 3;   // [16,512,3]

    zero_kernel<<<16, 256>>>(st, 4096);

    fps_kernel<<<NB, 1024>>>(pts, ctr, out_ctr);
    knn_kernel<<<BGc, 256>>>(pts, ctr, out_nbr);

    enc1_kernel<<<(M1 * 128) / 256, 256>>>(out_nbr, w1, b1, h1);
    bnstats_kernel<<<M1 / 512, 128>>>(h1, 128, s1a, s2a);
    bnfin_kernel<<<1, 128>>>(s1a, s2a, 1.0f / (float)M1, bn1g, bn1b, scale1, shift1);
    mmagemm_kernel<1, 0><<<dim3(2, 2048), 256, GE_SMEM>>>(h1, w2, b2, nullptr, f, M1, 256, 128, scale1, shift1);
    maxk_kernel<<<(BGc * 256) / 256, 256>>>(f, fg, 256, BGc * 256);
    mmagemm_kernel<2, 0><<<dim3(4, 2048), 256, GE_SMEM>>>(f, w3, b3, nullptr, h3, M1, 512, 512, fg, nullptr);
    bnstats_kernel<<<M1 / 512, 512>>>(h3, 512, s1b, s2b);
    bnfin_kernel<<<1, 512>>>(s1b, s2b, 1.0f / (float)M1, bn2g, bn2b, scale2, shift2);
    mmagemm_kernel<1, 0><<<dim3(3, 2048), 256, GE_SMEM>>>(h3, w4, b4, nullptr, f4, M1, 384, 512, scale2, shift2);
    maxk_kernel<<<(BGc * 384) / 256, 256>>>(f4, x, 384, BGc * 384);

    pos_kernel<<<BGc, 128>>>(ctr, pw1, pb1, pw2, pb2, pos);

    for (int l = 0; l < NL; l++) {
        add_kernel<<<(BGc * 384) / 256, 256>>>(x, pos, xin, BGc * 384);
        ln_kernel<<<BGc, 128>>>(xin, hln, ln1g + l * 384, ln1b + l * 384);
        mmagemm_kernel<0, 0><<<dim3(9, 64), 256, GE_SMEM>>>(hln, qkvw + (size_t)l * 384 * 1152,
                                                            nullptr, nullptr, qkv, BGc, 1152, 384,
                                                            nullptr, nullptr);
        attn_qk_kernel<<<dim3(8, 8, NB * NH), 256>>>(qkv, sc);
        softmax_kernel<<<NB * NH * 512, 128>>>(sc);
        attn_av_kernel<<<dim3(8, NB * NH), 256>>>(sc, qkv, ob);
        mmagemm_kernel<0, 1><<<dim3(3, 64), 256, GE_SMEM>>>(ob, projw + (size_t)l * 384 * 384,
                                                            projb + l * 384, xin, x, BGc, 384, 384,
                                                            nullptr, nullptr);
        ln_kernel<<<BGc, 128>>>(x, hln, ln2g + l * 384, ln2b + l * 384);
        mmagemm_kernel<0, 2><<<dim3(12, 64), 256, GE_SMEM>>>(hln, fc1w + (size_t)l * 384 * 1536,
                                                             fc1b + l * 1536, nullptr, ff, BGc, 1536, 384,
                                                             nullptr, nullptr);
        mmagemm_kernel<0, 1><<<dim3(3, 64), 256, GE_SMEM>>>(ff, fc2w + (size_t)l * 1536 * 384,
                                                            fc2b + l * 384, x, x, BGc, 384, 1536,
                                                            nullptr, nullptr);
    }
    ln_kernel<<<BGc, 128>>>(x, out_x, nfg, nfb);
}

// round 5
// speedup vs baseline: 1.4607x; 1.2775x over previous
#include <cuda_runtime.h>
#include <math.h>
#include <stdint.h>

// Problem dims
#define NB 16
#define NP 8192
#define NG 512
#define NK 32
#define ND 384
#define NL 12
#define NH 6
#define BGc (NB*NG)      /* 8192 */
#define M1  (BGc*NK)     /* 262144 */

// ---------------- scratch layout ----------------
constexpr size_t O_H1  = 0;
constexpr size_t O_F   = O_H1  + (size_t)M1*128;
constexpr size_t O_H3  = O_F   + (size_t)M1*256;
constexpr size_t O_F4  = O_H3  + (size_t)M1*512;
constexpr size_t O_FG  = O_F4  + (size_t)M1*384;
constexpr size_t O_X   = O_FG  + (size_t)BGc*256;
constexpr size_t O_XIN = O_X   + (size_t)BGc*384;
constexpr size_t O_HLN = O_XIN + (size_t)BGc*384;
constexpr size_t O_OB  = O_HLN + (size_t)BGc*384;
constexpr size_t O_POS = O_OB  + (size_t)BGc*384;
constexpr size_t O_QKV = O_POS + (size_t)BGc*384;
constexpr size_t O_SC  = O_QKV + (size_t)BGc*1152;
constexpr size_t O_FF  = O_SC  + (size_t)96*512*512;
constexpr size_t O_CTR = O_FF  + (size_t)BGc*1536;
constexpr size_t O_ST  = O_CTR + (size_t)BGc*3;
constexpr size_t SCRATCH_TOTAL = O_ST + 4096;

__device__ float g_scratch[SCRATCH_TOTAL];

__device__ __forceinline__ float gelu_f(float x) {
    return 0.5f * x * (1.0f + erff(x * 0.70710678118654752f));
}

// ---------------- bf16 helpers (baseline PTX, sm_80+) ----------------
// word = {bf16(x1) in high 16, bf16(x0) in low 16}; lo-word = residuals.
__device__ __forceinline__ void bf16x2_split(float x0, float x1, uint32_t& hi, uint32_t& lo) {
    uint32_t h;
    asm("cvt.rn.bf16x2.f32 %0, %1, %2;" : "=r"(h) : "f"(x1), "f"(x0));
    float h0 = __uint_as_float(h << 16);
    float h1 = __uint_as_float(h & 0xffff0000u);
    float r0 = x0 - h0, r1 = x1 - h1;
    asm("cvt.rn.bf16x2.f32 %0, %1, %2;" : "=r"(lo) : "f"(r1), "f"(r0));
    hi = h;
}

__device__ __forceinline__ void mma_bf16(float* d, const uint32_t* a, uint32_t b0, uint32_t b1) {
    asm volatile(
        "mma.sync.aligned.m16n8k16.row.col.f32.bf16.bf16.f32 "
        "{%0,%1,%2,%3}, {%4,%5,%6,%7}, {%8,%9}, {%0,%1,%2,%3};"
        : "+f"(d[0]), "+f"(d[1]), "+f"(d[2]), "+f"(d[3])
        : "r"(a[0]), "r"(a[1]), "r"(a[2]), "r"(a[3]), "r"(b0), "r"(b1));
}

// ============ BF16x3 mma.sync GEMM: 128x128 block tile, K in 32-chunks ============
// 8 warps: 4 warp-rows x 2 warp-cols; warp tile 32x64 (2 m16 x 8 n8 tiles)
// smem word layout per row: 2 k16-blocks x 8 word-slots; word w stored at
// slot (w&3)*2 + (w>>2)  => thread lt's frag words (lt, lt+4) are ADJACENT -> LDS.64.
// Row stride AW=24 words => conflict-free LDS.64 per 16-lane phase (verified).
// AMODE 0: plain A[M,K]; 1: relu(A*q0[k]+q1[k]); 2: concat(fg=q0[row/32], f=A[row]) K=512
// EPI   0: +bias; 1: +bias+res; 2: gelu(+bias)
#define AW 24
static constexpr int GE_SMEM = 4 * 128 * AW * 4;  // 49152 B

template <int AMODE, int EPI>
__global__ void __launch_bounds__(256) mmagemm_kernel(
    const float* __restrict__ A, const float* __restrict__ W,
    const float* __restrict__ bias, const float* __restrict__ res,
    float* __restrict__ C, int M, int N, int K,
    const float* __restrict__ q0, const float* __restrict__ q1) {
    extern __shared__ uint32_t sm[];
    uint32_t* Ahi = sm;                  // [128][AW]
    uint32_t* Alo = Ahi + 128 * AW;
    uint32_t* Bhi = Alo + 128 * AW;      // [n=128][AW]
    uint32_t* Blo = Bhi + 128 * AW;

    const int tid = threadIdx.x;
    const int warp = tid >> 5, lane = tid & 31;
    const int row0 = blockIdx.y << 7, col0 = blockIdx.x << 7;
    const int wr = (warp & 3) << 5;    // warp row base (0/32/64/96)
    const int wc = (warp >> 2) << 6;   // warp col base (0/64)

    float d[2][8][4];
#pragma unroll
    for (int mt = 0; mt < 2; mt++)
#pragma unroll
        for (int nt = 0; nt < 8; nt++)
#pragma unroll
            for (int i = 0; i < 4; i++) d[mt][nt][i] = 0.f;

    const int arow = tid >> 1;
    const int akoff = (tid & 1) << 4;    // 0 or 16 (k16 block within chunk)
    const int grow = row0 + arow;
    const int bn = tid & 127;
    const int bkoff = (tid >> 7) << 4;

    const int lg = lane >> 2;   // group id
    const int lt = lane & 3;    // thread in group

    const int nblk = K >> 5;
    for (int kb = 0; kb < nblk; kb++) {
        const int kbase = kb << 5;
        // ---- stage A (128 x 32): thread = (row, k16 half) ----
        {
            float v[16];
            const int kg = kbase + akoff;
            if (AMODE == 2) {
                const float* src = (kg < 256)
                    ? (q0 + ((size_t)(grow >> 5)) * 256 + kg)
                    : (A + ((size_t)grow) * 256 + (kg - 256));
#pragma unroll
                for (int i = 0; i < 4; i++) *(float4*)&v[i * 4] = *(const float4*)&src[i * 4];
            } else {
                const float* src = A + (size_t)grow * K + kg;
#pragma unroll
                for (int i = 0; i < 4; i++) *(float4*)&v[i * 4] = *(const float4*)&src[i * 4];
                if (AMODE == 1) {
#pragma unroll
                    for (int c = 0; c < 16; c++)
                        v[c] = fmaxf(fmaf(v[c], q0[kg + c], q1[kg + c]), 0.f);
                }
            }
            uint32_t* ah = Ahi + arow * AW + (akoff >> 4) * 8;
            uint32_t* al = Alo + arow * AW + (akoff >> 4) * 8;
#pragma unroll
            for (int u = 0; u < 4; u++) {
                uint32_t h1, l1, h2, l2;
                bf16x2_split(v[2 * u], v[2 * u + 1], h1, l1);        // word u (k 2u,2u+1)
                bf16x2_split(v[2 * u + 8], v[2 * u + 9], h2, l2);    // word u+4 (k 2u+8,2u+9)
                *(uint2*)(ah + 2 * u) = make_uint2(h1, h2);
                *(uint2*)(al + 2 * u) = make_uint2(l1, l2);
            }
        }
        // ---- stage B (32 x 128) into [n][k-word] layout ----
        {
            const float* wp = W + (size_t)(kbase + bkoff) * N + col0 + bn;
            uint32_t* bh = Bhi + bn * AW + (bkoff >> 4) * 8;
            uint32_t* bl = Blo + bn * AW + (bkoff >> 4) * 8;
#pragma unroll
            for (int u = 0; u < 4; u++) {
                uint32_t h1, l1, h2, l2;
                bf16x2_split(wp[(size_t)(2 * u) * N], wp[(size_t)(2 * u + 1) * N], h1, l1);
                bf16x2_split(wp[(size_t)(2 * u + 8) * N], wp[(size_t)(2 * u + 9) * N], h2, l2);
                *(uint2*)(bh + 2 * u) = make_uint2(h1, h2);
                *(uint2*)(bl + 2 * u) = make_uint2(l1, l2);
            }
        }
        __syncthreads();
#pragma unroll
        for (int b16 = 0; b16 < 2; b16++) {
            const int bo = b16 * 8 + 2 * lt;
            uint32_t ah[2][4], al[2][4];
#pragma unroll
            for (int mt = 0; mt < 2; mt++) {
                const int r1 = wr + mt * 16 + lg;
                uint2 t0 = *(const uint2*)(Ahi + r1 * AW + bo);        // a0, a2
                uint2 t1 = *(const uint2*)(Ahi + (r1 + 8) * AW + bo);  // a1, a3
                ah[mt][0] = t0.x; ah[mt][1] = t1.x; ah[mt][2] = t0.y; ah[mt][3] = t1.y;
                uint2 s0 = *(const uint2*)(Alo + r1 * AW + bo);
                uint2 s1 = *(const uint2*)(Alo + (r1 + 8) * AW + bo);
                al[mt][0] = s0.x; al[mt][1] = s1.x; al[mt][2] = s0.y; al[mt][3] = s1.y;
            }
#pragma unroll
            for (int nt = 0; nt < 8; nt++) {
                const int n = wc + nt * 8 + lg;
                uint2 bh = *(const uint2*)(Bhi + n * AW + bo);   // b0, b1
                uint2 bl = *(const uint2*)(Blo + n * AW + bo);
#pragma unroll
                for (int mt = 0; mt < 2; mt++) {
                    mma_bf16(d[mt][nt], ah[mt], bh.x, bh.y);
                    mma_bf16(d[mt][nt], al[mt], bh.x, bh.y);
                    mma_bf16(d[mt][nt], ah[mt], bl.x, bl.y);
                }
            }
        }
        __syncthreads();
    }

    // ---- epilogue ----
#pragma unroll
    for (int mt = 0; mt < 2; mt++) {
        const int r1 = row0 + wr + mt * 16 + lg;
        const int r2 = r1 + 8;
#pragma unroll
        for (int nt = 0; nt < 8; nt++) {
            const int c = col0 + wc + nt * 8 + lt * 2;
            float v0 = d[mt][nt][0], v1 = d[mt][nt][1];
            float v2 = d[mt][nt][2], v3 = d[mt][nt][3];
            if (bias) {
                float b0 = bias[c], b1 = bias[c + 1];
                v0 += b0; v1 += b1; v2 += b0; v3 += b1;
            }
            if (EPI == 1) {
                v0 += res[(size_t)r1 * N + c];
                v1 += res[(size_t)r1 * N + c + 1];
                v2 += res[(size_t)r2 * N + c];
                v3 += res[(size_t)r2 * N + c + 1];
            } else if (EPI == 2) {
                v0 = gelu_f(v0); v1 = gelu_f(v1); v2 = gelu_f(v2); v3 = gelu_f(v3);
            }
            C[(size_t)r1 * N + c]     = v0;
            C[(size_t)r1 * N + c + 1] = v1;
            C[(size_t)r2 * N + c]     = v2;
            C[(size_t)r2 * N + c + 1] = v3;
        }
    }
}

// ---------------- zero / add / maxk ----------------
__global__ void zero_kernel(float* p, int n) {
    int i = blockIdx.x * blockDim.x + threadIdx.x;
    if (i < n) p[i] = 0.0f;
}

__global__ void add_kernel(const float* __restrict__ a, const float* __restrict__ b,
                           float* __restrict__ c, int n) {
    int i = blockIdx.x * blockDim.x + threadIdx.x;
    if (i < n) c[i] = a[i] + b[i];
}

__global__ void maxk_kernel(const float* __restrict__ in, float* __restrict__ out,
                            int C, int total) {
    int idx = blockIdx.x * blockDim.x + threadIdx.x;
    if (idx >= total) return;
    int r = idx / C, c = idx - r * C;
    const float* p = in + ((size_t)r * 32) * C + c;
    float m = p[0];
#pragma unroll
    for (int t = 1; t < 32; t++) m = fmaxf(m, p[(size_t)t * C]);
    out[idx] = m;
}

// ---------------- FPS (warp-shuffle argmax reduction) ----------------
__global__ void __launch_bounds__(1024) fps_kernel(const float* __restrict__ pts,
                                                   float* __restrict__ ctr,
                                                   float* __restrict__ ctr_out) {
    int b = blockIdx.x;
    int tid = threadIdx.x, wid = tid >> 5, lane = tid & 31;
    const float* P = pts + (size_t)b * NP * 3;
    float px[8], py[8], pz[8], dl[8];
#pragma unroll
    for (int t = 0; t < 8; t++) {
        int j = tid + t * 1024;
        px[t] = P[j * 3 + 0]; py[t] = P[j * 3 + 1]; pz[t] = P[j * 3 + 2];
        dl[t] = 1e10f;
    }
    __shared__ float lastp[3];
    __shared__ float wv_s[32];
    __shared__ int   wi_s[32];
    if (tid == 0) {
        lastp[0] = P[0]; lastp[1] = P[1]; lastp[2] = P[2];
        size_t co = (size_t)b * NG * 3;
        ctr[co] = P[0]; ctr[co + 1] = P[1]; ctr[co + 2] = P[2];
        ctr_out[co] = P[0]; ctr_out[co + 1] = P[1]; ctr_out[co + 2] = P[2];
    }
    __syncthreads();
    for (int s = 1; s < NG; s++) {
        float lx = lastp[0], ly = lastp[1], lz = lastp[2];
        float bv = -1.0f; int bi = 0;
#pragma unroll
        for (int t = 0; t < 8; t++) {
            float dx = __fsub_rn(px[t], lx);
            float dy = __fsub_rn(py[t], ly);
            float dz = __fsub_rn(pz[t], lz);
            float d = __fadd_rn(__fadd_rn(__fmul_rn(dx, dx), __fmul_rn(dy, dy)),
                                __fmul_rn(dz, dz));
            float nd = fminf(dl[t], d);
            dl[t] = nd;
            if (nd > bv) { bv = nd; bi = tid + t * 1024; }
        }
#pragma unroll
        for (int o = 16; o; o >>= 1) {
            float v2 = __shfl_xor_sync(0xFFFFFFFFu, bv, o);
            int   i2 = __shfl_xor_sync(0xFFFFFFFFu, bi, o);
            if (v2 > bv || (v2 == bv && i2 < bi)) { bv = v2; bi = i2; }
        }
        if (lane == 0) { wv_s[wid] = bv; wi_s[wid] = bi; }
        __syncthreads();
        if (wid == 0) {
            bv = wv_s[lane]; bi = wi_s[lane];
#pragma unroll
            for (int o = 16; o; o >>= 1) {
                float v2 = __shfl_xor_sync(0xFFFFFFFFu, bv, o);
                int   i2 = __shfl_xor_sync(0xFFFFFFFFu, bi, o);
                if (v2 > bv || (v2 == bv && i2 < bi)) { bv = v2; bi = i2; }
            }
            if (lane == 0) {
                float qx = P[bi * 3], qy = P[bi * 3 + 1], qz = P[bi * 3 + 2];
                lastp[0] = qx; lastp[1] = qy; lastp[2] = qz;
                size_t co = ((size_t)b * NG + s) * 3;
                ctr[co] = qx; ctr[co + 1] = qy; ctr[co + 2] = qz;
                ctr_out[co] = qx; ctr_out[co + 1] = qy; ctr_out[co + 2] = qz;
            }
        }
        __syncthreads();
    }
}

// ---------------- KNN (bit-exact d2 vs reference) ----------------
__global__ void __launch_bounds__(256) knn_kernel(const float* __restrict__ pts,
                                                  const float* __restrict__ ctr,
                                                  float* __restrict__ nbr_out) {
    int bg = blockIdx.x;
    int b = bg >> 9;
    const float* P = pts + (size_t)b * NP * 3;
    float cx = ctr[bg * 3 + 0], cy = ctr[bg * 3 + 1], cz = ctr[bg * 3 + 2];
    float c2 = __fadd_rn(__fadd_rn(__fmul_rn(cx, cx), __fmul_rn(cy, cy)), __fmul_rn(cz, cz));
    __shared__ float d2s[NP];
    int tid = threadIdx.x;
    for (int j = tid; j < NP; j += 256) {
        float px = P[j * 3], py = P[j * 3 + 1], pz = P[j * 3 + 2];
        float p2 = __fadd_rn(__fadd_rn(__fmul_rn(px, px), __fmul_rn(py, py)), __fmul_rn(pz, pz));
        float dot = __fmaf_rn(cz, pz, __fmaf_rn(cy, py, __fmul_rn(cx, px)));
        d2s[j] = __fsub_rn(__fadd_rn(c2, p2), __fmul_rn(2.0f, dot));
    }
    __syncthreads();
    __shared__ float rv[256];
    __shared__ int ri[256];
    __shared__ int chosen[NK];
    for (int sel = 0; sel < NK; sel++) {
        float bv = 3.4e38f; int bi = 0x7fffffff;
        for (int j = tid; j < NP; j += 256) {
            float v = d2s[j];
            if (v < bv) { bv = v; bi = j; }
        }
        rv[tid] = bv; ri[tid] = bi;
        __syncthreads();
        for (int o = 128; o; o >>= 1) {
            if (tid < o) {
                float v2 = rv[tid + o]; int i2 = ri[tid + o];
                if (v2 < rv[tid] || (v2 == rv[tid] && i2 < ri[tid])) {
                    rv[tid] = v2; ri[tid] = i2;
                }
            }
            __syncthreads();
        }
        if (tid == 0) { chosen[sel] = ri[0]; d2s[ri[0]] = 3.4e38f; }
        __syncthreads();
    }
    if (tid < NK) {
        int j = chosen[tid];
        size_t o = ((size_t)bg * NK + tid) * 3;
        nbr_out[o + 0] = P[j * 3 + 0] - cx;
        nbr_out[o + 1] = P[j * 3 + 1] - cy;
        nbr_out[o + 2] = P[j * 3 + 2] - cz;
    }
}

// ---------------- encoder first linear 3->128 ----------------
__global__ void enc1_kernel(const float* __restrict__ nbr, const float* __restrict__ w1,
                            const float* __restrict__ b1, float* __restrict__ h1) {
    size_t idx = (size_t)blockIdx.x * blockDim.x + threadIdx.x;
    if (idx >= (size_t)M1 * 128) return;
    size_t i = idx >> 7;
    int c = (int)(idx & 127);
    float x0 = nbr[i * 3], x1 = nbr[i * 3 + 1], x2 = nbr[i * 3 + 2];
    h1[idx] = x0 * w1[c] + x1 * w1[128 + c] + x2 * w1[256 + c] + b1[c];
}

// ---------------- BN stats ----------------
__global__ void bnstats_kernel(const float* __restrict__ h, int C,
                               float* __restrict__ s1, float* __restrict__ s2) {
    int c = threadIdx.x;
    size_t r0 = (size_t)blockIdx.x * 512;
    const float* p = h + r0 * C + c;
    float a = 0.f, q = 0.f;
    for (int r = 0; r < 512; r++) {
        float v = p[(size_t)r * C];
        a += v; q += v * v;
    }
    atomicAdd(&s1[c], a);
    atomicAdd(&s2[c], q);
}

__global__ void bnfin_kernel(const float* __restrict__ s1, const float* __restrict__ s2,
                             float invM, const float* __restrict__ g, const float* __restrict__ b,
                             float* __restrict__ scale, float* __restrict__ shift) {
    int c = threadIdx.x;
    float mean = s1[c] * invM;
    float var = s2[c] * invM - mean * mean;
    float r = rsqrtf(var + 1e-5f);
    float sc = g[c] * r;
    scale[c] = sc;
    shift[c] = b[c] - mean * sc;
}

// ---------------- layernorm over D=384 ----------------
__global__ void __launch_bounds__(128) ln_kernel(const float* __restrict__ in,
                                                 float* __restrict__ out,
                                                 const float* __restrict__ gg,
                                                 const float* __restrict__ bb) {
    int row = blockIdx.x;
    int tid = threadIdx.x;
    const float* p = in + (size_t)row * 384;
    float v0 = p[tid], v1 = p[tid + 128], v2 = p[tid + 256];
    __shared__ float sh[128];
    sh[tid] = v0 + v1 + v2;
    __syncthreads();
    for (int o = 64; o; o >>= 1) { if (tid < o) sh[tid] += sh[tid + o]; __syncthreads(); }
    float mean = sh[0] * (1.0f / 384.0f);
    __syncthreads();
    float d0 = v0 - mean, d1 = v1 - mean, d2 = v2 - mean;
    sh[tid] = d0 * d0 + d1 * d1 + d2 * d2;
    __syncthreads();
    for (int o = 64; o; o >>= 1) { if (tid < o) sh[tid] += sh[tid + o]; __syncthreads(); }
    float rstd = rsqrtf(sh[0] * (1.0f / 384.0f) + 1e-5f);
    float* q = out + (size_t)row * 384;
    q[tid]       = d0 * rstd * gg[tid]       + bb[tid];
    q[tid + 128] = d1 * rstd * gg[tid + 128] + bb[tid + 128];
    q[tid + 256] = d2 * rstd * gg[tid + 256] + bb[tid + 256];
}

// ---------------- pos embed ----------------
__global__ void __launch_bounds__(128) pos_kernel(const float* __restrict__ ctr,
                                                  const float* __restrict__ pw1,
                                                  const float* __restrict__ pb1,
                                                  const float* __restrict__ pw2,
                                                  const float* __restrict__ pb2,
                                                  float* __restrict__ pos) {
    int row = blockIdx.x;
    int tid = threadIdx.x;
    float cx = ctr[row * 3], cy = ctr[row * 3 + 1], cz = ctr[row * 3 + 2];
    __shared__ float t[128];
    float u = cx * pw1[tid] + cy * pw1[128 + tid] + cz * pw1[256 + tid] + pb1[tid];
    t[tid] = gelu_f(u);
    __syncthreads();
    for (int j = tid; j < 384; j += 128) {
        float s = pb2[j];
#pragma unroll 8
        for (int k = 0; k < 128; k++) s = fmaf(t[k], pw2[k * 384 + j], s);
        pos[(size_t)row * 384 + j] = s;
    }
}

// ---------------- attention: S = scale * Q K^T ----------------
__global__ void __launch_bounds__(256) attn_qk_kernel(const float* __restrict__ qkv,
                                                      float* __restrict__ S) {
    int z = blockIdx.z;
    int b = z / NH, h = z - b * NH;
    const float* Qb = qkv + ((size_t)b * NG) * 1152 + h * 64;
    const float* Kb = Qb + 384;
    int m0 = blockIdx.y * 64, n0 = blockIdx.x * 64;
    __shared__ float Qs[16][65], Ks[16][65];
    int tid = threadIdx.x, tx = tid & 15, ty = tid >> 4;
    int lr = tid >> 2, lc = (tid & 3) * 4;
    float acc[4][4];
#pragma unroll
    for (int i = 0; i < 4; i++)
#pragma unroll
        for (int j = 0; j < 4; j++) acc[i][j] = 0.f;
    for (int d0 = 0; d0 < 64; d0 += 16) {
        float4 qv = *(const float4*)&Qb[(size_t)(m0 + lr) * 1152 + d0 + lc];
        float4 kv = *(const float4*)&Kb[(size_t)(n0 + lr) * 1152 + d0 + lc];
        Qs[lc + 0][lr] = qv.x; Qs[lc + 1][lr] = qv.y; Qs[lc + 2][lr] = qv.z; Qs[lc + 3][lr] = qv.w;
        Ks[lc + 0][lr] = kv.x; Ks[lc + 1][lr] = kv.y; Ks[lc + 2][lr] = kv.z; Ks[lc + 3][lr] = kv.w;
        __syncthreads();
#pragma unroll
        for (int kk = 0; kk < 16; kk++) {
            float a[4], w[4];
#pragma unroll
            for (int i = 0; i < 4; i++) a[i] = Qs[kk][ty * 4 + i];
#pragma unroll
            for (int j = 0; j < 4; j++) w[j] = Ks[kk][tx * 4 + j];
#pragma unroll
            for (int i = 0; i < 4; i++)
#pragma unroll
                for (int j = 0; j < 4; j++) acc[i][j] = fmaf(a[i], w[j], acc[i][j]);
        }
        __syncthreads();
    }
    float* out = S + (size_t)z * 512 * 512;
#pragma unroll
    for (int i = 0; i < 4; i++)
#pragma unroll
        for (int j = 0; j < 4; j++)
            out[(size_t)(m0 + ty * 4 + i) * 512 + n0 + tx * 4 + j] = acc[i][j] * 0.125f;
}

__global__ void __launch_bounds__(128) softmax_kernel(float* __restrict__ S) {
    size_t row = blockIdx.x;
    float* p = S + row * 512;
    int tid = threadIdx.x;
    float v[4];
#pragma unroll
    for (int u = 0; u < 4; u++) v[u] = p[tid + u * 128];
    float m = fmaxf(fmaxf(v[0], v[1]), fmaxf(v[2], v[3]));
    __shared__ float sh[128];
    sh[tid] = m;
    __syncthreads();
    for (int o = 64; o; o >>= 1) { if (tid < o) sh[tid] = fmaxf(sh[tid], sh[tid + o]); __syncthreads(); }
    m = sh[0];
    __syncthreads();
    float s = 0.f;
#pragma unroll
    for (int u = 0; u < 4; u++) { v[u] = expf(v[u] - m); s += v[u]; }
    sh[tid] = s;
    __syncthreads();
    for (int o = 64; o; o >>= 1) { if (tid < o) sh[tid] += sh[tid + o]; __syncthreads(); }
    float inv = 1.0f / sh[0];
#pragma unroll
    for (int u = 0; u < 4; u++) p[tid + u * 128] = v[u] * inv;
}

// ---------------- attention: O = A V ----------------
__global__ void __launch_bounds__(256) attn_av_kernel(const float* __restrict__ S,
                                                      const float* __restrict__ qkv,
                                                      float* __restrict__ O) {
    int z = blockIdx.y;
    int b = z / NH, h = z - b * NH;
    const float* A = S + (size_t)z * 512 * 512;
    const float* Vb = qkv + ((size_t)b * NG) * 1152 + 768 + h * 64;
    int m0 = blockIdx.x * 64;
    __shared__ float As[16][65], Vs[16][64];
    int tid = threadIdx.x, tx = tid & 15, ty = tid >> 4;
    int lr = tid >> 2, lc = (tid & 3) * 4;
    int vr = tid >> 4, vc = (tid & 15) * 4;
    float acc[4][4];
#pragma unroll
    for (int i = 0; i < 4; i++)
#pragma unroll
        for (int j = 0; j < 4; j++) acc[i][j] = 0.f;
    for (int n0 = 0; n0 < 512; n0 += 16) {
        float4 avv = *(const float4*)&A[(size_t)(m0 + lr) * 512 + n0 + lc];
        As[lc + 0][lr] = avv.x; As[lc + 1][lr] = avv.y; As[lc + 2][lr] = avv.z; As[lc + 3][lr] = avv.w;
        float4 vv = *(const float4*)&Vb[(size_t)(n0 + vr) * 1152 + vc];
        *(float4*)&Vs[vr][vc] = vv;
        __syncthreads();
#pragma unroll
        for (int kk = 0; kk < 16; kk++) {
            float a[4], w[4];
#pragma unroll
            for (int i = 0; i < 4; i++) a[i] = As[kk][ty * 4 + i];
#pragma unroll
            for (int j = 0; j < 4; j++) w[j] = Vs[kk][tx * 4 + j];
#pragma unroll
            for (int i = 0; i < 4; i++)
#pragma unroll
                for (int j = 0; j < 4; j++) acc[i][j] = fmaf(a[i], w[j], acc[i][j]);
        }
        __syncthreads();
    }
    float* Ob = O + ((size_t)b * NG) * 384 + h * 64;
#pragma unroll
    for (int i = 0; i < 4; i++)
#pragma unroll
        for (int j = 0; j < 4; j++)
            Ob[(size_t)(m0 + ty * 4 + i) * 384 + tx * 4 + j] = acc[i][j];
}

// ---------------- host ----------------
extern "C" void kernel_launch(void* const* d_in, const int* in_sizes, int n_in,
                              void* d_out, int out_size) {
    const float* pts   = (const float*)d_in[0];
    const float* w1    = (const float*)d_in[1];
    const float* b1    = (const float*)d_in[2];
    const float* bn1g  = (const float*)d_in[3];
    const float* bn1b  = (const float*)d_in[4];
    const float* w2    = (const float*)d_in[5];
    const float* b2    = (const float*)d_in[6];
    const float* w3    = (const float*)d_in[7];
    const float* b3    = (const float*)d_in[8];
    const float* bn2g  = (const float*)d_in[9];
    const float* bn2b  = (const float*)d_in[10];
    const float* w4    = (const float*)d_in[11];
    const float* b4    = (const float*)d_in[12];
    const float* pw1   = (const float*)d_in[13];
    const float* pb1   = (const float*)d_in[14];
    const float* pw2   = (const float*)d_in[15];
    const float* pb2   = (const float*)d_in[16];
    const float* ln1g  = (const float*)d_in[17];
    const float* ln1b  = (const float*)d_in[18];
    const float* qkvw  = (const float*)d_in[19];
    const float* projw = (const float*)d_in[20];
    const float* projb = (const float*)d_in[21];
    const float* ln2g  = (const float*)d_in[22];
    const float* ln2b  = (const float*)d_in[23];
    const float* fc1w  = (const float*)d_in[24];
    const float* fc1b  = (const float*)d_in[25];
    const float* fc2w  = (const float*)d_in[26];
    const float* fc2b  = (const float*)d_in[27];
    const float* nfg   = (const float*)d_in[28];
    const float* nfb   = (const float*)d_in[29];

    static float* S = nullptr;
    if (!S) {
        cudaGetSymbolAddress((void**)&S, g_scratch);
        cudaFuncSetAttribute(mmagemm_kernel<0, 0>, cudaFuncAttributeMaxDynamicSharedMemorySize, GE_SMEM);
        cudaFuncSetAttribute(mmagemm_kernel<0, 1>, cudaFuncAttributeMaxDynamicSharedMemorySize, GE_SMEM);
        cudaFuncSetAttribute(mmagemm_kernel<0, 2>, cudaFuncAttributeMaxDynamicSharedMemorySize, GE_SMEM);
        cudaFuncSetAttribute(mmagemm_kernel<1, 0>, cudaFuncAttributeMaxDynamicSharedMemorySize, GE_SMEM);
        cudaFuncSetAttribute(mmagemm_kernel<2, 0>, cudaFuncAttributeMaxDynamicSharedMemorySize, GE_SMEM);
    }

    float* h1   = S + O_H1;
    float* f    = S + O_F;
    float* h3   = S + O_H3;
    float* f4   = S + O_F4;
    float* fg   = S + O_FG;
    float* x    = S + O_X;
    float* xin  = S + O_XIN;
    float* hln  = S + O_HLN;
    float* ob   = S + O_OB;
    float* pos  = S + O_POS;
    float* qkv  = S + O_QKV;
    float* sc   = S + O_SC;
    float* ff   = S + O_FF;
    float* ctr  = S + O_CTR;
    float* st   = S + O_ST;
    float* s1a = st, *s2a = st + 128, *s1b = st + 256, *s2b = st + 768;
    float* scale1 = st + 1280, *shift1 = st + 1408;
    float* scale2 = st + 1536, *shift2 = st + 2048;

    float* out     = (float*)d_out;
    float* out_x   = out;                              // [16,512,384]
    float* out_nbr = out + (size_t)BGc * 384;          // [16,512,32,3]
    float* out_ctr = out_nbr + (size_t)BGc * NK * 3;   // [16,512,3]

    zero_kernel<<<16, 256>>>(st, 4096);

    fps_kernel<<<NB, 1024>>>(pts, ctr, out_ctr);
    knn_kernel<<<BGc, 256>>>(pts, ctr, out_nbr);

    enc1_kernel<<<(M1 * 128) / 256, 256>>>(out_nbr, w1, b1, h1);
    bnstats_kernel<<<M1 / 512, 128>>>(h1, 128, s1a, s2a);
    bnfin_kernel<<<1, 128>>>(s1a, s2a, 1.0f / (float)M1, bn1g, bn1b, scale1, shift1);
    mmagemm_kernel<1, 0><<<dim3(2, 2048), 256, GE_SMEM>>>(h1, w2, b2, nullptr, f, M1, 256, 128, scale1, shift1);
    maxk_kernel<<<(BGc * 256) / 256, 256>>>(f, fg, 256, BGc * 256);
    mmagemm_kernel<2, 0><<<dim3(4, 2048), 256, GE_SMEM>>>(f, w3, b3, nullptr, h3, M1, 512, 512, fg, nullptr);
    bnstats_kernel<<<M1 / 512, 512>>>(h3, 512, s1b, s2b);
    bnfin_kernel<<<1, 512>>>(s1b, s2b, 1.0f / (float)M1, bn2g, bn2b, scale2, shift2);
    mmagemm_kernel<1, 0><<<dim3(3, 2048), 256, GE_SMEM>>>(h3, w4, b4, nullptr, f4, M1, 384, 512, scale2, shift2);
    maxk_kernel<<<(BGc * 384) / 256, 256>>>(f4, x, 384, BGc * 384);

    pos_kernel<<<BGc, 128>>>(ctr, pw1, pb1, pw2, pb2, pos);

    for (int l = 0; l < NL; l++) {
        add_kernel<<<(BGc * 384) / 256, 256>>>(x, pos, xin, BGc * 384);
        ln_kernel<<<BGc, 128>>>(xin, hln, ln1g + l * 384, ln1b + l * 384);
        mmagemm_kernel<0, 0><<<dim3(9, 64), 256, GE_SMEM>>>(hln, qkvw + (size_t)l * 384 * 1152,
                                                            nullptr, nullptr, qkv, BGc, 1152, 384,
                                                            nullptr, nullptr);
        attn_qk_kernel<<<dim3(8, 8, NB * NH), 256>>>(qkv, sc);
        softmax_kernel<<<NB * NH * 512, 128>>>(sc);
        attn_av_kernel<<<dim3(8, NB * NH), 256>>>(sc, qkv, ob);
        mmagemm_kernel<0, 1><<<dim3(3, 64), 256, GE_SMEM>>>(ob, projw + (size_t)l * 384 * 384,
                                                            projb + l * 384, xin, x, BGc, 384, 384,
                                                            nullptr, nullptr);
        ln_kernel<<<BGc, 128>>>(x, hln, ln2g + l * 384, ln2b + l * 384);
        mmagemm_kernel<0, 2><<<dim3(12, 64), 256, GE_SMEM>>>(hln, fc1w + (size_t)l * 384 * 1536,
                                                             fc1b + l * 1536, nullptr, ff, BGc, 1536, 384,
                                                             nullptr, nullptr);
        mmagemm_kernel<0, 1><<<dim3(3, 64), 256, GE_SMEM>>>(ff, fc2w + (size_t)l * 1536 * 384,
                                                            fc2b + l * 384, x, x, BGc, 384, 1536,
                                                            nullptr, nullptr);
    }
    ln_kernel<<<BGc, 128>>>(x, out_x, nfg, nfb);
}

// round 6
// speedup vs baseline: 1.9176x; 1.3128x over previous
#include <cuda_runtime.h>
#include <math.h>
#include <stdint.h>

// Problem dims
#define NB 16
#define NP 8192
#define NG 512
#define NK 32
#define ND 384
#define NL 12
#define NH 6
#define BGc (NB*NG)      /* 8192 */
#define M1  (BGc*NK)     /* 262144 */

// ---------------- scratch layout ----------------
constexpr size_t O_H1  = 0;
constexpr size_t O_F   = O_H1  + (size_t)M1*128;
constexpr size_t O_H3  = O_F   + (size_t)M1*256;
constexpr size_t O_F4  = O_H3  + (size_t)M1*512;
constexpr size_t O_FG  = O_F4  + (size_t)M1*384;
constexpr size_t O_X   = O_FG  + (size_t)BGc*256;
constexpr size_t O_XIN = O_X   + (size_t)BGc*384;
constexpr size_t O_HLN = O_XIN + (size_t)BGc*384;
constexpr size_t O_OB  = O_HLN + (size_t)BGc*384;
constexpr size_t O_POS = O_OB  + (size_t)BGc*384;
constexpr size_t O_QKV = O_POS + (size_t)BGc*384;
constexpr size_t O_SC  = O_QKV + (size_t)BGc*1152;
constexpr size_t O_FF  = O_SC  + (size_t)96*512*512;
constexpr size_t O_CTR = O_FF  + (size_t)BGc*1536;
constexpr size_t O_ST  = O_CTR + (size_t)BGc*3;
constexpr size_t SCRATCH_TOTAL = O_ST + 4096;

__device__ float g_scratch[SCRATCH_TOTAL];

__device__ __forceinline__ float gelu_f(float x) {
    return 0.5f * x * (1.0f + erff(x * 0.70710678118654752f));
}

// ---------------- bf16 helpers ----------------
__device__ __forceinline__ void bf16x2_split(float x0, float x1, uint32_t& hi, uint32_t& lo) {
    uint32_t h;
    asm("cvt.rn.bf16x2.f32 %0, %1, %2;" : "=r"(h) : "f"(x1), "f"(x0));
    float h0 = __uint_as_float(h << 16);
    float h1 = __uint_as_float(h & 0xffff0000u);
    float r0 = x0 - h0, r1 = x1 - h1;
    asm("cvt.rn.bf16x2.f32 %0, %1, %2;" : "=r"(lo) : "f"(r1), "f"(r0));
    hi = h;
}

__device__ __forceinline__ void mma_bf16(float* d, const uint32_t* a, uint32_t b0, uint32_t b1) {
    asm volatile(
        "mma.sync.aligned.m16n8k16.row.col.f32.bf16.bf16.f32 "
        "{%0,%1,%2,%3}, {%4,%5,%6,%7}, {%8,%9}, {%0,%1,%2,%3};"
        : "+f"(d[0]), "+f"(d[1]), "+f"(d[2]), "+f"(d[3])
        : "r"(a[0]), "r"(a[1]), "r"(a[2]), "r"(a[3]), "r"(b0), "r"(b1));
}

#define AW 24
#define BUFW (4 * 128 * AW)                       /* 12288 words per buffer */
static constexpr int GE_SMEM = 2 * BUFW * 4;      /* 98304 B (double-buffered) */
static constexpr int QK_SMEM = BUFW * 4;          /* 49152 B */
static constexpr int AV_SMEM = (3 * 128 * AW + 2 * 64 * AW) * 4;  /* A(hi,lo)+B(hi,lo) */

// ============ BF16x3 mma.sync GEMM, double-buffered ============
template <int AMODE, int EPI>
__global__ void __launch_bounds__(256) mmagemm_kernel(
    const float* __restrict__ A, const float* __restrict__ W,
    const float* __restrict__ bias, const float* __restrict__ res,
    float* __restrict__ C, int M, int N, int K,
    const float* __restrict__ q0, const float* __restrict__ q1) {
    extern __shared__ uint32_t sm[];

    const int tid = threadIdx.x;
    const int warp = tid >> 5, lane = tid & 31;
    const int row0 = blockIdx.y << 7, col0 = blockIdx.x << 7;
    const int wr = (warp & 3) << 5;
    const int wc = (warp >> 2) << 6;

    float d[2][8][4];
#pragma unroll
    for (int mt = 0; mt < 2; mt++)
#pragma unroll
        for (int nt = 0; nt < 8; nt++)
#pragma unroll
            for (int i = 0; i < 4; i++) d[mt][nt][i] = 0.f;

    const int arow = tid >> 1;
    const int akoff = (tid & 1) << 4;
    const int grow = row0 + arow;
    const int bn = tid & 127;
    const int bkoff = (tid >> 7) << 4;
    const int lg = lane >> 2;
    const int lt = lane & 3;

    auto stage = [&](int kb, uint32_t* base) {
        uint32_t* Ahi = base;
        uint32_t* Alo = base + 3072;
        uint32_t* Bhi = base + 6144;
        uint32_t* Blo = base + 9216;
        const int kbase = kb << 5;
        {
            float v[16];
            const int kg = kbase + akoff;
            if (AMODE == 2) {
                const float* src = (kg < 256)
                    ? (q0 + ((size_t)(grow >> 5)) * 256 + kg)
                    : (A + ((size_t)grow) * 256 + (kg - 256));
#pragma unroll
                for (int i = 0; i < 4; i++) *(float4*)&v[i * 4] = *(const float4*)&src[i * 4];
            } else {
                const float* src = A + (size_t)grow * K + kg;
#pragma unroll
                for (int i = 0; i < 4; i++) *(float4*)&v[i * 4] = *(const float4*)&src[i * 4];
                if (AMODE == 1) {
#pragma unroll
                    for (int c = 0; c < 16; c++)
                        v[c] = fmaxf(fmaf(v[c], q0[kg + c], q1[kg + c]), 0.f);
                }
            }
            uint32_t* ah = Ahi + arow * AW + (akoff >> 4) * 8;
            uint32_t* al = Alo + arow * AW + (akoff >> 4) * 8;
#pragma unroll
            for (int u = 0; u < 4; u++) {
                uint32_t h1, l1, h2, l2;
                bf16x2_split(v[2 * u], v[2 * u + 1], h1, l1);
                bf16x2_split(v[2 * u + 8], v[2 * u + 9], h2, l2);
                *(uint2*)(ah + 2 * u) = make_uint2(h1, h2);
                *(uint2*)(al + 2 * u) = make_uint2(l1, l2);
            }
        }
        {
            const float* wp = W + (size_t)(kbase + bkoff) * N + col0 + bn;
            uint32_t* bh = Bhi + bn * AW + (bkoff >> 4) * 8;
            uint32_t* bl = Blo + bn * AW + (bkoff >> 4) * 8;
#pragma unroll
            for (int u = 0; u < 4; u++) {
                uint32_t h1, l1, h2, l2;
                bf16x2_split(wp[(size_t)(2 * u) * N], wp[(size_t)(2 * u + 1) * N], h1, l1);
                bf16x2_split(wp[(size_t)(2 * u + 8) * N], wp[(size_t)(2 * u + 9) * N], h2, l2);
                *(uint2*)(bh + 2 * u) = make_uint2(h1, h2);
                *(uint2*)(bl + 2 * u) = make_uint2(l1, l2);
            }
        }
    };

    auto compute = [&](const uint32_t* base) {
        const uint32_t* Ahi = base;
        const uint32_t* Alo = base + 3072;
        const uint32_t* Bhi = base + 6144;
        const uint32_t* Blo = base + 9216;
#pragma unroll
        for (int b16 = 0; b16 < 2; b16++) {
            const int bo = b16 * 8 + 2 * lt;
            uint32_t ah[2][4], al[2][4];
#pragma unroll
            for (int mt = 0; mt < 2; mt++) {
                const int r1 = wr + mt * 16 + lg;
                uint2 t0 = *(const uint2*)(Ahi + r1 * AW + bo);
                uint2 t1 = *(const uint2*)(Ahi + (r1 + 8) * AW + bo);
                ah[mt][0] = t0.x; ah[mt][1] = t1.x; ah[mt][2] = t0.y; ah[mt][3] = t1.y;
                uint2 s0 = *(const uint2*)(Alo + r1 * AW + bo);
                uint2 s1 = *(const uint2*)(Alo + (r1 + 8) * AW + bo);
                al[mt][0] = s0.x; al[mt][1] = s1.x; al[mt][2] = s0.y; al[mt][3] = s1.y;
            }
#pragma unroll
            for (int nt = 0; nt < 8; nt++) {
                const int n = wc + nt * 8 + lg;
                uint2 bh = *(const uint2*)(Bhi + n * AW + bo);
                uint2 bl = *(const uint2*)(Blo + n * AW + bo);
#pragma unroll
                for (int mt = 0; mt < 2; mt++) {
                    mma_bf16(d[mt][nt], ah[mt], bh.x, bh.y);
                    mma_bf16(d[mt][nt], al[mt], bh.x, bh.y);
                    mma_bf16(d[mt][nt], ah[mt], bl.x, bl.y);
                }
            }
        }
    };

    const int nblk = K >> 5;
    stage(0, sm);
    __syncthreads();
    for (int kb = 0; kb < nblk; kb++) {
        compute(sm + (kb & 1) * BUFW);
        if (kb + 1 < nblk) stage(kb + 1, sm + ((kb + 1) & 1) * BUFW);
        __syncthreads();
    }

    // ---- epilogue ----
#pragma unroll
    for (int mt = 0; mt < 2; mt++) {
        const int r1 = row0 + wr + mt * 16 + lg;
        const int r2 = r1 + 8;
#pragma unroll
        for (int nt = 0; nt < 8; nt++) {
            const int c = col0 + wc + nt * 8 + lt * 2;
            float v0 = d[mt][nt][0], v1 = d[mt][nt][1];
            float v2 = d[mt][nt][2], v3 = d[mt][nt][3];
            if (bias) {
                float b0 = bias[c], b1 = bias[c + 1];
                v0 += b0; v1 += b1; v2 += b0; v3 += b1;
            }
            if (EPI == 1) {
                v0 += res[(size_t)r1 * N + c];
                v1 += res[(size_t)r1 * N + c + 1];
                v2 += res[(size_t)r2 * N + c];
                v3 += res[(size_t)r2 * N + c + 1];
            } else if (EPI == 2) {
                v0 = gelu_f(v0); v1 = gelu_f(v1); v2 = gelu_f(v2); v3 = gelu_f(v3);
            }
            C[(size_t)r1 * N + c]     = v0;
            C[(size_t)r1 * N + c + 1] = v1;
            C[(size_t)r2 * N + c]     = v2;
            C[(size_t)r2 * N + c + 1] = v3;
        }
    }
}

// ============ attention QK: S = 0.125 * Q K^T (bf16x3 mma) ============
__global__ void __launch_bounds__(256) attn_qk_mma(const float* __restrict__ qkv,
                                                   float* __restrict__ S) {
    extern __shared__ uint32_t sm[];
    uint32_t* Ahi = sm;
    uint32_t* Alo = sm + 3072;
    uint32_t* Bhi = sm + 6144;
    uint32_t* Blo = sm + 9216;
    const int z = blockIdx.z;
    const int b = z / NH, h = z - b * NH;
    const float* Qb = qkv + (size_t)b * NG * 1152 + h * 64;
    const float* Kb = Qb + 384;
    const int m0 = blockIdx.y << 7, n0 = blockIdx.x << 7;
    const int tid = threadIdx.x;
    const int warp = tid >> 5, lane = tid & 31;
    const int wr = (warp & 3) << 5, wc = (warp >> 2) << 6;
    const int arow = tid >> 1, akoff = (tid & 1) << 4;
    const int lg = lane >> 2, lt = lane & 3;

    float d[2][8][4];
#pragma unroll
    for (int mt = 0; mt < 2; mt++)
#pragma unroll
        for (int nt = 0; nt < 8; nt++)
#pragma unroll
            for (int i = 0; i < 4; i++) d[mt][nt][i] = 0.f;

#pragma unroll
    for (int kb = 0; kb < 2; kb++) {
        const int kg = (kb << 5) + akoff;
        {
            const float* src = Qb + (size_t)(m0 + arow) * 1152 + kg;
            uint32_t* ah = Ahi + arow * AW + (akoff >> 4) * 8;
            uint32_t* al = Alo + arow * AW + (akoff >> 4) * 8;
            float v[16];
#pragma unroll
            for (int i = 0; i < 4; i++) *(float4*)&v[i * 4] = *(const float4*)&src[i * 4];
#pragma unroll
            for (int u = 0; u < 4; u++) {
                uint32_t h1, l1, h2, l2;
                bf16x2_split(v[2 * u], v[2 * u + 1], h1, l1);
                bf16x2_split(v[2 * u + 8], v[2 * u + 9], h2, l2);
                *(uint2*)(ah + 2 * u) = make_uint2(h1, h2);
                *(uint2*)(al + 2 * u) = make_uint2(l1, l2);
            }
        }
        {
            const float* src = Kb + (size_t)(n0 + arow) * 1152 + kg;
            uint32_t* bh = Bhi + arow * AW + (akoff >> 4) * 8;
            uint32_t* bl = Blo + arow * AW + (akoff >> 4) * 8;
            float v[16];
#pragma unroll
            for (int i = 0; i < 4; i++) *(float4*)&v[i * 4] = *(const float4*)&src[i * 4];
#pragma unroll
            for (int u = 0; u < 4; u++) {
                uint32_t h1, l1, h2, l2;
                bf16x2_split(v[2 * u], v[2 * u + 1], h1, l1);
                bf16x2_split(v[2 * u + 8], v[2 * u + 9], h2, l2);
                *(uint2*)(bh + 2 * u) = make_uint2(h1, h2);
                *(uint2*)(bl + 2 * u) = make_uint2(l1, l2);
            }
        }
        __syncthreads();
#pragma unroll
        for (int b16 = 0; b16 < 2; b16++) {
            const int bo = b16 * 8 + 2 * lt;
            uint32_t ah[2][4], al[2][4];
#pragma unroll
            for (int mt = 0; mt < 2; mt++) {
                const int r1 = wr + mt * 16 + lg;
                uint2 t0 = *(const uint2*)(Ahi + r1 * AW + bo);
                uint2 t1 = *(const uint2*)(Ahi + (r1 + 8) * AW + bo);
                ah[mt][0] = t0.x; ah[mt][1] = t1.x; ah[mt][2] = t0.y; ah[mt][3] = t1.y;
                uint2 s0 = *(const uint2*)(Alo + r1 * AW + bo);
                uint2 s1 = *(const uint2*)(Alo + (r1 + 8) * AW + bo);
                al[mt][0] = s0.x; al[mt][1] = s1.x; al[mt][2] = s0.y; al[mt][3] = s1.y;
            }
#pragma unroll
            for (int nt = 0; nt < 8; nt++) {
                const int n = wc + nt * 8 + lg;
                uint2 bh = *(const uint2*)(Bhi + n * AW + bo);
                uint2 bl = *(const uint2*)(Blo + n * AW + bo);
#pragma unroll
                for (int mt = 0; mt < 2; mt++) {
                    mma_bf16(d[mt][nt], ah[mt], bh.x, bh.y);
                    mma_bf16(d[mt][nt], al[mt], bh.x, bh.y);
                    mma_bf16(d[mt][nt], ah[mt], bl.x, bl.y);
                }
            }
        }
        __syncthreads();
    }
    float* out = S + (size_t)z * 512 * 512;
#pragma unroll
    for (int mt = 0; mt < 2; mt++) {
        const int r1 = m0 + wr + mt * 16 + lg;
        const int r2 = r1 + 8;
#pragma unroll
        for (int nt = 0; nt < 8; nt++) {
            const int c = n0 + wc + nt * 8 + lt * 2;
            out[(size_t)r1 * 512 + c]     = d[mt][nt][0] * 0.125f;
            out[(size_t)r1 * 512 + c + 1] = d[mt][nt][1] * 0.125f;
            out[(size_t)r2 * 512 + c]     = d[mt][nt][2] * 0.125f;
            out[(size_t)r2 * 512 + c + 1] = d[mt][nt][3] * 0.125f;
        }
    }
}

// ============ attention AV: O = A V (bf16x3 mma), tile 128x64 ============
__global__ void __launch_bounds__(256) attn_av_mma(const float* __restrict__ S,
                                                   const float* __restrict__ qkv,
                                                   float* __restrict__ O) {
    extern __shared__ uint32_t sm[];
    uint32_t* Ahi = sm;
    uint32_t* Alo = sm + 3072;
    uint32_t* Bhi = sm + 6144;
    uint32_t* Blo = sm + 6144 + 64 * AW;
    const int z = blockIdx.y;
    const int b = z / NH, h = z - b * NH;
    const float* A = S + (size_t)z * 512 * 512;
    const float* Vb = qkv + (size_t)b * NG * 1152 + 768 + h * 64;
    const int m0 = blockIdx.x << 7;
    const int tid = threadIdx.x;
    const int warp = tid >> 5, lane = tid & 31;
    const int wr = (warp & 3) << 5, wc = (warp >> 2) << 5;
    const int arow = tid >> 1, akoff = (tid & 1) << 4;
    const int bn = tid & 63, bhalf = (tid >> 6) & 1, brep = tid >> 7;
    const int lg = lane >> 2, lt = lane & 3;

    float d[2][4][4];
#pragma unroll
    for (int mt = 0; mt < 2; mt++)
#pragma unroll
        for (int nt = 0; nt < 4; nt++)
#pragma unroll
            for (int i = 0; i < 4; i++) d[mt][nt][i] = 0.f;

    for (int kb = 0; kb < 16; kb++) {
        const int kbase = kb << 5;
        {
            const float* src = A + (size_t)(m0 + arow) * 512 + kbase + akoff;
            uint32_t* ah = Ahi + arow * AW + (akoff >> 4) * 8;
            uint32_t* al = Alo + arow * AW + (akoff >> 4) * 8;
            float v[16];
#pragma unroll
            for (int i = 0; i < 4; i++) *(float4*)&v[i * 4] = *(const float4*)&src[i * 4];
#pragma unroll
            for (int u = 0; u < 4; u++) {
                uint32_t h1, l1, h2, l2;
                bf16x2_split(v[2 * u], v[2 * u + 1], h1, l1);
                bf16x2_split(v[2 * u + 8], v[2 * u + 9], h2, l2);
                *(uint2*)(ah + 2 * u) = make_uint2(h1, h2);
                *(uint2*)(al + 2 * u) = make_uint2(l1, l2);
            }
        }
        {
            uint32_t* bh = Bhi + bn * AW + bhalf * 8;
            uint32_t* bl = Blo + bn * AW + bhalf * 8;
#pragma unroll
            for (int p = 0; p < 4; p++) {
                const int k0 = kbase + bhalf * 16 + brep * 8 + 2 * p;
                float v0 = Vb[(size_t)k0 * 1152 + bn];
                float v1 = Vb[(size_t)(k0 + 1) * 1152 + bn];
                uint32_t hh, ll;
                bf16x2_split(v0, v1, hh, ll);
                bh[2 * p + brep] = hh;
                bl[2 * p + brep] = ll;
            }
        }
        __syncthreads();
#pragma unroll
        for (int b16 = 0; b16 < 2; b16++) {
            const int bo = b16 * 8 + 2 * lt;
            uint32_t ah[2][4], al[2][4];
#pragma unroll
            for (int mt = 0; mt < 2; mt++) {
                const int r1 = wr + mt * 16 + lg;
                uint2 t0 = *(const uint2*)(Ahi + r1 * AW + bo);
                uint2 t1 = *(const uint2*)(Ahi + (r1 + 8) * AW + bo);
                ah[mt][0] = t0.x; ah[mt][1] = t1.x; ah[mt][2] = t0.y; ah[mt][3] = t1.y;
                uint2 s0 = *(const uint2*)(Alo + r1 * AW + bo);
                uint2 s1 = *(const uint2*)(Alo + (r1 + 8) * AW + bo);
                al[mt][0] = s0.x; al[mt][1] = s1.x; al[mt][2] = s0.y; al[mt][3] = s1.y;
            }
#pragma unroll
            for (int nt = 0; nt < 4; nt++) {
                const int n = wc + nt * 8 + lg;
                uint2 bh = *(const uint2*)(Bhi + n * AW + bo);
                uint2 bl = *(const uint2*)(Blo + n * AW + bo);
#pragma unroll
                for (int mt = 0; mt < 2; mt++) {
                    mma_bf16(d[mt][nt], ah[mt], bh.x, bh.y);
                    mma_bf16(d[mt][nt], al[mt], bh.x, bh.y);
                    mma_bf16(d[mt][nt], ah[mt], bl.x, bl.y);
                }
            }
        }
        __syncthreads();
    }
    float* Ob = O + (size_t)b * NG * 384 + h * 64;
#pragma unroll
    for (int mt = 0; mt < 2; mt++) {
        const int r1 = m0 + wr + mt * 16 + lg;
        const int r2 = r1 + 8;
#pragma unroll
        for (int nt = 0; nt < 4; nt++) {
            const int c = wc + nt * 8 + lt * 2;
            Ob[(size_t)r1 * 384 + c]     = d[mt][nt][0];
            Ob[(size_t)r1 * 384 + c + 1] = d[mt][nt][1];
            Ob[(size_t)r2 * 384 + c]     = d[mt][nt][2];
            Ob[(size_t)r2 * 384 + c + 1] = d[mt][nt][3];
        }
    }
}

// ---------------- zero / maxk ----------------
__global__ void zero_kernel(float* p, int n) {
    int i = blockIdx.x * blockDim.x + threadIdx.x;
    if (i < n) p[i] = 0.0f;
}

__global__ void maxk_kernel(const float* __restrict__ in, float* __restrict__ out,
                            int C, int total) {
    int idx = blockIdx.x * blockDim.x + threadIdx.x;
    if (idx >= total) return;
    int r = idx / C, c = idx - r * C;
    const float* p = in + ((size_t)r * 32) * C + c;
    float m = p[0];
#pragma unroll
    for (int t = 1; t < 32; t++) m = fmaxf(m, p[(size_t)t * C]);
    out[idx] = m;
}

// ---------------- FPS ----------------
__global__ void __launch_bounds__(1024) fps_kernel(const float* __restrict__ pts,
                                                   float* __restrict__ ctr,
                                                   float* __restrict__ ctr_out) {
    int b = blockIdx.x;
    int tid = threadIdx.x, wid = tid >> 5, lane = tid & 31;
    const float* P = pts + (size_t)b * NP * 3;
    float px[8], py[8], pz[8], dl[8];
#pragma unroll
    for (int t = 0; t < 8; t++) {
        int j = tid + t * 1024;
        px[t] = P[j * 3 + 0]; py[t] = P[j * 3 + 1]; pz[t] = P[j * 3 + 2];
        dl[t] = 1e10f;
    }
    __shared__ float lastp[3];
    __shared__ float wv_s[32];
    __shared__ int   wi_s[32];
    if (tid == 0) {
        lastp[0] = P[0]; lastp[1] = P[1]; lastp[2] = P[2];
        size_t co = (size_t)b * NG * 3;
        ctr[co] = P[0]; ctr[co + 1] = P[1]; ctr[co + 2] = P[2];
        ctr_out[co] = P[0]; ctr_out[co + 1] = P[1]; ctr_out[co + 2] = P[2];
    }
    __syncthreads();
    for (int s = 1; s < NG; s++) {
        float lx = lastp[0], ly = lastp[1], lz = lastp[2];
        float bv = -1.0f; int bi = 0;
#pragma unroll
        for (int t = 0; t < 8; t++) {
            float dx = __fsub_rn(px[t], lx);
            float dy = __fsub_rn(py[t], ly);
            float dz = __fsub_rn(pz[t], lz);
            float d = __fadd_rn(__fadd_rn(__fmul_rn(dx, dx), __fmul_rn(dy, dy)),
                                __fmul_rn(dz, dz));
            float nd = fminf(dl[t], d);
            dl[t] = nd;
            if (nd > bv) { bv = nd; bi = tid + t * 1024; }
        }
#pragma unroll
        for (int o = 16; o; o >>= 1) {
            float v2 = __shfl_xor_sync(0xFFFFFFFFu, bv, o);
            int   i2 = __shfl_xor_sync(0xFFFFFFFFu, bi, o);
            if (v2 > bv || (v2 == bv && i2 < bi)) { bv = v2; bi = i2; }
        }
        if (lane == 0) { wv_s[wid] = bv; wi_s[wid] = bi; }
        __syncthreads();
        if (wid == 0) {
            bv = wv_s[lane]; bi = wi_s[lane];
#pragma unroll
            for (int o = 16; o; o >>= 1) {
                float v2 = __shfl_xor_sync(0xFFFFFFFFu, bv, o);
                int   i2 = __shfl_xor_sync(0xFFFFFFFFu, bi, o);
                if (v2 > bv || (v2 == bv && i2 < bi)) { bv = v2; bi = i2; }
            }
            if (lane == 0) {
                float qx = P[bi * 3], qy = P[bi * 3 + 1], qz = P[bi * 3 + 2];
                lastp[0] = qx; lastp[1] = qy; lastp[2] = qz;
                size_t co = ((size_t)b * NG + s) * 3;
                ctr[co] = qx; ctr[co + 1] = qy; ctr[co + 2] = qz;
                ctr_out[co] = qx; ctr_out[co + 1] = qy; ctr_out[co + 2] = qz;
            }
        }
        __syncthreads();
    }
}

// ---------------- KNN ----------------
__global__ void __launch_bounds__(256) knn_kernel(const float* __restrict__ pts,
                                                  const float* __restrict__ ctr,
                                                  float* __restrict__ nbr_out) {
    int bg = blockIdx.x;
    int b = bg >> 9;
    const float* P = pts + (size_t)b * NP * 3;
    float cx = ctr[bg * 3 + 0], cy = ctr[bg * 3 + 1], cz = ctr[bg * 3 + 2];
    float c2 = __fadd_rn(__fadd_rn(__fmul_rn(cx, cx), __fmul_rn(cy, cy)), __fmul_rn(cz, cz));
    __shared__ float d2s[NP];
    int tid = threadIdx.x;
    for (int j = tid; j < NP; j += 256) {
        float px = P[j * 3], py = P[j * 3 + 1], pz = P[j * 3 + 2];
        float p2 = __fadd_rn(__fadd_rn(__fmul_rn(px, px), __fmul_rn(py, py)), __fmul_rn(pz, pz));
        float dot = __fmaf_rn(cz, pz, __fmaf_rn(cy, py, __fmul_rn(cx, px)));
        d2s[j] = __fsub_rn(__fadd_rn(c2, p2), __fmul_rn(2.0f, dot));
    }
    __syncthreads();
    __shared__ float rv[256];
    __shared__ int ri[256];
    __shared__ int chosen[NK];
    for (int sel = 0; sel < NK; sel++) {
        float bv = 3.4e38f; int bi = 0x7fffffff;
        for (int j = tid; j < NP; j += 256) {
            float v = d2s[j];
            if (v < bv) { bv = v; bi = j; }
        }
        rv[tid] = bv; ri[tid] = bi;
        __syncthreads();
        for (int o = 128; o; o >>= 1) {
            if (tid < o) {
                float v2 = rv[tid + o]; int i2 = ri[tid + o];
                if (v2 < rv[tid] || (v2 == rv[tid] && i2 < ri[tid])) {
                    rv[tid] = v2; ri[tid] = i2;
                }
            }
            __syncthreads();
        }
        if (tid == 0) { chosen[sel] = ri[0]; d2s[ri[0]] = 3.4e38f; }
        __syncthreads();
    }
    if (tid < NK) {
        int j = chosen[tid];
        size_t o = ((size_t)bg * NK + tid) * 3;
        nbr_out[o + 0] = P[j * 3 + 0] - cx;
        nbr_out[o + 1] = P[j * 3 + 1] - cy;
        nbr_out[o + 2] = P[j * 3 + 2] - cz;
    }
}

// ---------------- encoder first linear 3->128 ----------------
__global__ void enc1_kernel(const float* __restrict__ nbr, const float* __restrict__ w1,
                            const float* __restrict__ b1, float* __restrict__ h1) {
    size_t idx = (size_t)blockIdx.x * blockDim.x + threadIdx.x;
    if (idx >= (size_t)M1 * 128) return;
    size_t i = idx >> 7;
    int c = (int)(idx & 127);
    float x0 = nbr[i * 3], x1 = nbr[i * 3 + 1], x2 = nbr[i * 3 + 2];
    h1[idx] = x0 * w1[c] + x1 * w1[128 + c] + x2 * w1[256 + c] + b1[c];
}

// ---------------- BN stats ----------------
__global__ void bnstats_kernel(const float* __restrict__ h, int C,
                               float* __restrict__ s1, float* __restrict__ s2) {
    int c = threadIdx.x;
    size_t r0 = (size_t)blockIdx.x * 512;
    const float* p = h + r0 * C + c;
    float a = 0.f, q = 0.f;
    for (int r = 0; r < 512; r++) {
        float v = p[(size_t)r * C];
        a += v; q += v * v;
    }
    atomicAdd(&s1[c], a);
    atomicAdd(&s2[c], q);
}

__global__ void bnfin_kernel(const float* __restrict__ s1, const float* __restrict__ s2,
                             float invM, const float* __restrict__ g, const float* __restrict__ b,
                             float* __restrict__ scale, float* __restrict__ shift) {
    int c = threadIdx.x;
    float mean = s1[c] * invM;
    float var = s2[c] * invM - mean * mean;
    float r = rsqrtf(var + 1e-5f);
    float sc = g[c] * r;
    scale[c] = sc;
    shift[c] = b[c] - mean * sc;
}

// ---------------- layernorm (optionally fused with add) ----------------
__global__ void __launch_bounds__(128) ln_kernel(const float* __restrict__ in,
                                                 float* __restrict__ out,
                                                 const float* __restrict__ gg,
                                                 const float* __restrict__ bb) {
    int row = blockIdx.x;
    int tid = threadIdx.x;
    const float* p = in + (size_t)row * 384;
    float v0 = p[tid], v1 = p[tid + 128], v2 = p[tid + 256];
    __shared__ float sh[128];
    sh[tid] = v0 + v1 + v2;
    __syncthreads();
    for (int o = 64; o; o >>= 1) { if (tid < o) sh[tid] += sh[tid + o]; __syncthreads(); }
    float mean = sh[0] * (1.0f / 384.0f);
    __syncthreads();
    float d0 = v0 - mean, d1 = v1 - mean, d2 = v2 - mean;
    sh[tid] = d0 * d0 + d1 * d1 + d2 * d2;
    __syncthreads();
    for (int o = 64; o; o >>= 1) { if (tid < o) sh[tid] += sh[tid + o]; __syncthreads(); }
    float rstd = rsqrtf(sh[0] * (1.0f / 384.0f) + 1e-5f);
    float* q = out + (size_t)row * 384;
    q[tid]       = d0 * rstd * gg[tid]       + bb[tid];
    q[tid + 128] = d1 * rstd * gg[tid + 128] + bb[tid + 128];
    q[tid + 256] = d2 * rstd * gg[tid + 256] + bb[tid + 256];
}

// xin = x + pos; out = LN(xin)
__global__ void __launch_bounds__(128) ln_add_kernel(const float* __restrict__ x,
                                                     const float* __restrict__ pos,
                                                     float* __restrict__ xin,
                                                     float* __restrict__ out,
                                                     const float* __restrict__ gg,
                                                     const float* __restrict__ bb) {
    int row = blockIdx.x;
    int tid = threadIdx.x;
    const float* p = x + (size_t)row * 384;
    const float* pp = pos + (size_t)row * 384;
    float v0 = p[tid] + pp[tid];
    float v1 = p[tid + 128] + pp[tid + 128];
    float v2 = p[tid + 256] + pp[tid + 256];
    float* xo = xin + (size_t)row * 384;
    xo[tid] = v0; xo[tid + 128] = v1; xo[tid + 256] = v2;
    __shared__ float sh[128];
    sh[tid] = v0 + v1 + v2;
    __syncthreads();
    for (int o = 64; o; o >>= 1) { if (tid < o) sh[tid] += sh[tid + o]; __syncthreads(); }
    float mean = sh[0] * (1.0f / 384.0f);
    __syncthreads();
    float d0 = v0 - mean, d1 = v1 - mean, d2 = v2 - mean;
    sh[tid] = d0 * d0 + d1 * d1 + d2 * d2;
    __syncthreads();
    for (int o = 64; o; o >>= 1) { if (tid < o) sh[tid] += sh[tid + o]; __syncthreads(); }
    float rstd = rsqrtf(sh[0] * (1.0f / 384.0f) + 1e-5f);
    float* q = out + (size_t)row * 384;
    q[tid]       = d0 * rstd * gg[tid]       + bb[tid];
    q[tid + 128] = d1 * rstd * gg[tid + 128] + bb[tid + 128];
    q[tid + 256] = d2 * rstd * gg[tid + 256] + bb[tid + 256];
}

// ---------------- pos embed ----------------
__global__ void __launch_bounds__(128) pos_kernel(const float* __restrict__ ctr,
                                                  const float* __restrict__ pw1,
                                                  const float* __restrict__ pb1,
                                                  const float* __restrict__ pw2,
                                                  const float* __restrict__ pb2,
                                                  float* __restrict__ pos) {
    int row = blockIdx.x;
    int tid = threadIdx.x;
    float cx = ctr[row * 3], cy = ctr[row * 3 + 1], cz = ctr[row * 3 + 2];
    __shared__ float t[128];
    float u = cx * pw1[tid] + cy * pw1[128 + tid] + cz * pw1[256 + tid] + pb1[tid];
    t[tid] = gelu_f(u);
    __syncthreads();
    for (int j = tid; j < 384; j += 128) {
        float s = pb2[j];
#pragma unroll 8
        for (int k = 0; k < 128; k++) s = fmaf(t[k], pw2[k * 384 + j], s);
        pos[(size_t)row * 384 + j] = s;
    }
}

__global__ void __launch_bounds__(128) softmax_kernel(float* __restrict__ S) {
    size_t row = blockIdx.x;
    float* p = S + row * 512;
    int tid = threadIdx.x;
    float v[4];
#pragma unroll
    for (int u = 0; u < 4; u++) v[u] = p[tid + u * 128];
    float m = fmaxf(fmaxf(v[0], v[1]), fmaxf(v[2], v[3]));
    __shared__ float sh[128];
    sh[tid] = m;
    __syncthreads();
    for (int o = 64; o; o >>= 1) { if (tid < o) sh[tid] = fmaxf(sh[tid], sh[tid + o]); __syncthreads(); }
    m = sh[0];
    __syncthreads();
    float s = 0.f;
#pragma unroll
    for (int u = 0; u < 4; u++) { v[u] = expf(v[u] - m); s += v[u]; }
    sh[tid] = s;
    __syncthreads();
    for (int o = 64; o; o >>= 1) { if (tid < o) sh[tid] += sh[tid + o]; __syncthreads(); }
    float inv = 1.0f / sh[0];
#pragma unroll
    for (int u = 0; u < 4; u++) p[tid + u * 128] = v[u] * inv;
}

// ---------------- host ----------------
extern "C" void kernel_launch(void* const* d_in, const int* in_sizes, int n_in,
                              void* d_out, int out_size) {
    const float* pts   = (const float*)d_in[0];
    const float* w1    = (const float*)d_in[1];
    const float* b1    = (const float*)d_in[2];
    const float* bn1g  = (const float*)d_in[3];
    const float* bn1b  = (const float*)d_in[4];
    const float* w2    = (const float*)d_in[5];
    const float* b2    = (const float*)d_in[6];
    const float* w3    = (const float*)d_in[7];
    const float* b3    = (const float*)d_in[8];
    const float* bn2g  = (const float*)d_in[9];
    const float* bn2b  = (const float*)d_in[10];
    const float* w4    = (const float*)d_in[11];
    const float* b4    = (const float*)d_in[12];
    const float* pw1   = (const float*)d_in[13];
    const float* pb1   = (const float*)d_in[14];
    const float* pw2   = (const float*)d_in[15];
    const float* pb2   = (const float*)d_in[16];
    const float* ln1g  = (const float*)d_in[17];
    const float* ln1b  = (const float*)d_in[18];
    const float* qkvw  = (const float*)d_in[19];
    const float* projw = (const float*)d_in[20];
    const float* projb = (const float*)d_in[21];
    const float* ln2g  = (const float*)d_in[22];
    const float* ln2b  = (const float*)d_in[23];
    const float* fc1w  = (const float*)d_in[24];
    const float* fc1b  = (const float*)d_in[25];
    const float* fc2w  = (const float*)d_in[26];
    const float* fc2b  = (const float*)d_in[27];
    const float* nfg   = (const float*)d_in[28];
    const float* nfb   = (const float*)d_in[29];

    static float* S = nullptr;
    if (!S) {
        cudaGetSymbolAddress((void**)&S, g_scratch);
        cudaFuncSetAttribute(mmagemm_kernel<0, 0>, cudaFuncAttributeMaxDynamicSharedMemorySize, GE_SMEM);
        cudaFuncSetAttribute(mmagemm_kernel<0, 1>, cudaFuncAttributeMaxDynamicSharedMemorySize, GE_SMEM);
        cudaFuncSetAttribute(mmagemm_kernel<0, 2>, cudaFuncAttributeMaxDynamicSharedMemorySize, GE_SMEM);
        cudaFuncSetAttribute(mmagemm_kernel<1, 0>, cudaFuncAttributeMaxDynamicSharedMemorySize, GE_SMEM);
        cudaFuncSetAttribute(mmagemm_kernel<2, 0>, cudaFuncAttributeMaxDynamicSharedMemorySize, GE_SMEM);
        cudaFuncSetAttribute(attn_qk_mma, cudaFuncAttributeMaxDynamicSharedMemorySize, QK_SMEM);
        cudaFuncSetAttribute(attn_av_mma, cudaFuncAttributeMaxDynamicSharedMemorySize, AV_SMEM);
    }

    float* h1   = S + O_H1;
    float* f    = S + O_F;
    float* h3   = S + O_H3;
    float* f4   = S + O_F4;
    float* fg   = S + O_FG;
    float* x    = S + O_X;
    float* xin  = S + O_XIN;
    float* hln  = S + O_HLN;
    float* ob   = S + O_OB;
    float* pos  = S + O_POS;
    float* qkv  = S + O_QKV;
    float* sc   = S + O_SC;
    float* ff   = S + O_FF;
    float* ctr  = S + O_CTR;
    float* st   = S + O_ST;
    float* s1a = st, *s2a = st + 128, *s1b = st + 256, *s2b = st + 768;
    float* scale1 = st + 1280, *shift1 = st + 1408;
    float* scale2 = st + 1536, *shift2 = st + 2048;

    float* out     = (float*)d_out;
    float* out_x   = out;                              // [16,512,384]
    float* out_nbr = out + (size_t)BGc * 384;          // [16,512,32,3]
    float* out_ctr = out_nbr + (size_t)BGc * NK * 3;   // [16,512,3]

    zero_kernel<<<16, 256>>>(st, 4096);

    fps_kernel<<<NB, 1024>>>(pts, ctr, out_ctr);
    knn_kernel<<<BGc, 256>>>(pts, ctr, out_nbr);

    enc1_kernel<<<(M1 * 128) / 256, 256>>>(out_nbr, w1, b1, h1);
    bnstats_kernel<<<M1 / 512, 128>>>(h1, 128, s1a, s2a);
    bnfin_kernel<<<1, 128>>>(s1a, s2a, 1.0f / (float)M1, bn1g, bn1b, scale1, shift1);
    mmagemm_kernel<1, 0><<<dim3(2, 2048), 256, GE_SMEM>>>(h1, w2, b2, nullptr, f, M1, 256, 128, scale1, shift1);
    maxk_kernel<<<(BGc * 256) / 256, 256>>>(f, fg, 256, BGc * 256);
    mmagemm_kernel<2, 0><<<dim3(4, 2048), 256, GE_SMEM>>>(f, w3, b3, nullptr, h3, M1, 512, 512, fg, nullptr);
    bnstats_kernel<<<M1 / 512, 512>>>(h3, 512, s1b, s2b);
    bnfin_kernel<<<1, 512>>>(s1b, s2b, 1.0f / (float)M1, bn2g, bn2b, scale2, shift2);
    mmagemm_kernel<1, 0><<<dim3(3, 2048), 256, GE_SMEM>>>(h3, w4, b4, nullptr, f4, M1, 384, 512, scale2, shift2);
    maxk_kernel<<<(BGc * 384) / 256, 256>>>(f4, x, 384, BGc * 384);

    pos_kernel<<<BGc, 128>>>(ctr, pw1, pb1, pw2, pb2, pos);

    for (int l = 0; l < NL; l++) {
        ln_add_kernel<<<BGc, 128>>>(x, pos, xin, hln, ln1g + l * 384, ln1b + l * 384);
        mmagemm_kernel<0, 0><<<dim3(9, 64), 256, GE_SMEM>>>(hln, qkvw + (size_t)l * 384 * 1152,
                                                            nullptr, nullptr, qkv, BGc, 1152, 384,
                                                            nullptr, nullptr);
        attn_qk_mma<<<dim3(4, 4, NB * NH), 256, QK_SMEM>>>(qkv, sc);
        softmax_kernel<<<NB * NH * 512, 128>>>(sc);
        attn_av_mma<<<dim3(4, NB * NH), 256, AV_SMEM>>>(sc, qkv, ob);
        mmagemm_kernel<0, 1><<<dim3(3, 64), 256, GE_SMEM>>>(ob, projw + (size_t)l * 384 * 384,
                                                            projb + l * 384, xin, x, BGc, 384, 384,
                                                            nullptr, nullptr);
        ln_kernel<<<BGc, 128>>>(x, hln, ln2g + l * 384, ln2b + l * 384);
        mmagemm_kernel<0, 2><<<dim3(12, 64), 256, GE_SMEM>>>(hln, fc1w + (size_t)l * 384 * 1536,
                                                             fc1b + l * 1536, nullptr, ff, BGc, 1536, 384,
                                                             nullptr, nullptr);
        mmagemm_kernel<0, 1><<<dim3(3, 64), 256, GE_SMEM>>>(ff, fc2w + (size_t)l * 1536 * 384,
                                                            fc2b + l * 384, x, x, BGc, 384, 1536,
                                                            nullptr, nullptr);
    }
    ln_kernel<<<BGc, 128>>>(x, out_x, nfg, nfb);
}

// round 7
// speedup vs baseline: 2.0383x; 1.0630x over previous
#include <cuda_runtime.h>
#include <math.h>
#include <stdint.h>

// Problem dims
#define NB 16
#define NP 8192
#define NG 512
#define NK 32
#define ND 384
#define NL 12
#define NH 6
#define BGc (NB*NG)      /* 8192 */
#define M1  (BGc*NK)     /* 262144 */

// ---------------- scratch layout ----------------
constexpr size_t O_H1  = 0;
constexpr size_t O_F   = O_H1  + (size_t)M1*128;
constexpr size_t O_H3  = O_F   + (size_t)M1*256;
constexpr size_t O_F4  = O_H3  + (size_t)M1*512;   /* unused now, kept for layout stability */
constexpr size_t O_FG  = O_F4  + (size_t)M1*384;
constexpr size_t O_X   = O_FG  + (size_t)BGc*256;
constexpr size_t O_XIN = O_X   + (size_t)BGc*384;
constexpr size_t O_HLN = O_XIN + (size_t)BGc*384;
constexpr size_t O_OB  = O_HLN + (size_t)BGc*384;
constexpr size_t O_POS = O_OB  + (size_t)BGc*384;
constexpr size_t O_QKV = O_POS + (size_t)BGc*384;
constexpr size_t O_SC  = O_QKV + (size_t)BGc*1152;
constexpr size_t O_FF  = O_SC  + (size_t)96*512*512;
constexpr size_t O_CTR = O_FF  + (size_t)BGc*1536;
constexpr size_t O_ST  = O_CTR + (size_t)BGc*3;
constexpr size_t SCRATCH_TOTAL = O_ST + 4096;

__device__ float g_scratch[SCRATCH_TOTAL];

__device__ __forceinline__ float gelu_f(float x) {
    return 0.5f * x * (1.0f + erff(x * 0.70710678118654752f));
}

// ---------------- bf16 helpers ----------------
__device__ __forceinline__ void bf16x2_split(float x0, float x1, uint32_t& hi, uint32_t& lo) {
    uint32_t h;
    asm("cvt.rn.bf16x2.f32 %0, %1, %2;" : "=r"(h) : "f"(x1), "f"(x0));
    float h0 = __uint_as_float(h << 16);
    float h1 = __uint_as_float(h & 0xffff0000u);
    float r0 = x0 - h0, r1 = x1 - h1;
    asm("cvt.rn.bf16x2.f32 %0, %1, %2;" : "=r"(lo) : "f"(r1), "f"(r0));
    hi = h;
}

__device__ __forceinline__ void mma_bf16(float* d, const uint32_t* a, uint32_t b0, uint32_t b1) {
    asm volatile(
        "mma.sync.aligned.m16n8k16.row.col.f32.bf16.bf16.f32 "
        "{%0,%1,%2,%3}, {%4,%5,%6,%7}, {%8,%9}, {%0,%1,%2,%3};"
        : "+f"(d[0]), "+f"(d[1]), "+f"(d[2]), "+f"(d[3])
        : "r"(a[0]), "r"(a[1]), "r"(a[2]), "r"(a[3]), "r"(b0), "r"(b1));
}

#define AW 24
#define BUFW (4 * 128 * AW)                       /* 12288 words per buffer */
static constexpr int GE_SMEM = 2 * BUFW * 4;      /* 98304 B (double-buffered) */
static constexpr int QK_SMEM = BUFW * 4;          /* 49152 B */
static constexpr int AV_SMEM = (3 * 128 * AW + 2 * 64 * AW) * 4;

// ============ BF16x3 mma.sync GEMM, double-buffered ============
// AMODE 0: plain A[M,K]; 1: relu(A*q0[k]+q1[k])
// EPI 0: +bias; 1: +bias+res[r]; 2: gelu(+bias); 3: +res[(r>>5)] (group base);
// EPI 4: group-max only -> C[g*N+c] (bias added post-max);
// EPI 5: +bias write C AND group-max -> gout[g*N+c]
template <int AMODE, int EPI>
__global__ void __launch_bounds__(256) mmagemm_kernel(
    const float* __restrict__ A, const float* __restrict__ W,
    const float* __restrict__ bias, const float* __restrict__ res,
    float* __restrict__ C, int M, int N, int K,
    const float* __restrict__ q0, const float* __restrict__ q1,
    float* __restrict__ gout) {
    extern __shared__ uint32_t sm[];

    const int tid = threadIdx.x;
    const int warp = tid >> 5, lane = tid & 31;
    const int row0 = blockIdx.y << 7, col0 = blockIdx.x << 7;
    const int wr = (warp & 3) << 5;
    const int wc = (warp >> 2) << 6;

    float d[2][8][4];
#pragma unroll
    for (int mt = 0; mt < 2; mt++)
#pragma unroll
        for (int nt = 0; nt < 8; nt++)
#pragma unroll
            for (int i = 0; i < 4; i++) d[mt][nt][i] = 0.f;

    const int arow = tid >> 1;
    const int akoff = (tid & 1) << 4;
    const int grow = row0 + arow;
    const int bn = tid & 127;
    const int bkoff = (tid >> 7) << 4;
    const int lg = lane >> 2;
    const int lt = lane & 3;

    auto stage = [&](int kb, uint32_t* base) {
        uint32_t* Ahi = base;
        uint32_t* Alo = base + 3072;
        uint32_t* Bhi = base + 6144;
        uint32_t* Blo = base + 9216;
        const int kbase = kb << 5;
        {
            float v[16];
            const int kg = kbase + akoff;
            const float* src = A + (size_t)grow * K + kg;
#pragma unroll
            for (int i = 0; i < 4; i++) *(float4*)&v[i * 4] = *(const float4*)&src[i * 4];
            if (AMODE == 1) {
#pragma unroll
                for (int c = 0; c < 16; c++)
                    v[c] = fmaxf(fmaf(v[c], q0[kg + c], q1[kg + c]), 0.f);
            }
            uint32_t* ah = Ahi + arow * AW + (akoff >> 4) * 8;
            uint32_t* al = Alo + arow * AW + (akoff >> 4) * 8;
#pragma unroll
            for (int u = 0; u < 4; u++) {
                uint32_t h1, l1, h2, l2;
                bf16x2_split(v[2 * u], v[2 * u + 1], h1, l1);
                bf16x2_split(v[2 * u + 8], v[2 * u + 9], h2, l2);
                *(uint2*)(ah + 2 * u) = make_uint2(h1, h2);
                *(uint2*)(al + 2 * u) = make_uint2(l1, l2);
            }
        }
        {
            const float* wp = W + (size_t)(kbase + bkoff) * N + col0 + bn;
            uint32_t* bh = Bhi + bn * AW + (bkoff >> 4) * 8;
            uint32_t* bl = Blo + bn * AW + (bkoff >> 4) * 8;
#pragma unroll
            for (int u = 0; u < 4; u++) {
                uint32_t h1, l1, h2, l2;
                bf16x2_split(wp[(size_t)(2 * u) * N], wp[(size_t)(2 * u + 1) * N], h1, l1);
                bf16x2_split(wp[(size_t)(2 * u + 8) * N], wp[(size_t)(2 * u + 9) * N], h2, l2);
                *(uint2*)(bh + 2 * u) = make_uint2(h1, h2);
                *(uint2*)(bl + 2 * u) = make_uint2(l1, l2);
            }
        }
    };

    auto compute = [&](const uint32_t* base) {
        const uint32_t* Ahi = base;
        const uint32_t* Alo = base + 3072;
        const uint32_t* Bhi = base + 6144;
        const uint32_t* Blo = base + 9216;
#pragma unroll
        for (int b16 = 0; b16 < 2; b16++) {
            const int bo = b16 * 8 + 2 * lt;
            uint32_t ah[2][4], al[2][4];
#pragma unroll
            for (int mt = 0; mt < 2; mt++) {
                const int r1 = wr + mt * 16 + lg;
                uint2 t0 = *(const uint2*)(Ahi + r1 * AW + bo);
                uint2 t1 = *(const uint2*)(Ahi + (r1 + 8) * AW + bo);
                ah[mt][0] = t0.x; ah[mt][1] = t1.x; ah[mt][2] = t0.y; ah[mt][3] = t1.y;
                uint2 s0 = *(const uint2*)(Alo + r1 * AW + bo);
                uint2 s1 = *(const uint2*)(Alo + (r1 + 8) * AW + bo);
                al[mt][0] = s0.x; al[mt][1] = s1.x; al[mt][2] = s0.y; al[mt][3] = s1.y;
            }
#pragma unroll
            for (int nt = 0; nt < 8; nt++) {
                const int n = wc + nt * 8 + lg;
                uint2 bh = *(const uint2*)(Bhi + n * AW + bo);
                uint2 bl = *(const uint2*)(Blo + n * AW + bo);
#pragma unroll
                for (int mt = 0; mt < 2; mt++) {
                    mma_bf16(d[mt][nt], ah[mt], bh.x, bh.y);
                    mma_bf16(d[mt][nt], al[mt], bh.x, bh.y);
                    mma_bf16(d[mt][nt], ah[mt], bl.x, bl.y);
                }
            }
        }
    };

    const int nblk = K >> 5;
    stage(0, sm);
    __syncthreads();
    for (int kb = 0; kb < nblk; kb++) {
        compute(sm + (kb & 1) * BUFW);
        if (kb + 1 < nblk) stage(kb + 1, sm + ((kb + 1) & 1) * BUFW);
        __syncthreads();
    }

    const int g = (row0 + wr) >> 5;

    // ---- per-row epilogue ----
    if (EPI <= 3 || EPI == 5) {
#pragma unroll
        for (int mt = 0; mt < 2; mt++) {
            const int r1 = row0 + wr + mt * 16 + lg;
            const int r2 = r1 + 8;
#pragma unroll
            for (int nt = 0; nt < 8; nt++) {
                const int c = col0 + wc + nt * 8 + lt * 2;
                float v0 = d[mt][nt][0], v1 = d[mt][nt][1];
                float v2 = d[mt][nt][2], v3 = d[mt][nt][3];
                if (bias) {
                    float b0 = bias[c], b1 = bias[c + 1];
                    v0 += b0; v1 += b1; v2 += b0; v3 += b1;
                }
                if (EPI == 1) {
                    v0 += res[(size_t)r1 * N + c];
                    v1 += res[(size_t)r1 * N + c + 1];
                    v2 += res[(size_t)r2 * N + c];
                    v3 += res[(size_t)r2 * N + c + 1];
                } else if (EPI == 3) {
                    float g0 = res[(size_t)g * N + c];
                    float g1 = res[(size_t)g * N + c + 1];
                    v0 += g0; v1 += g1; v2 += g0; v3 += g1;
                } else if (EPI == 2) {
                    v0 = gelu_f(v0); v1 = gelu_f(v1); v2 = gelu_f(v2); v3 = gelu_f(v3);
                }
                C[(size_t)r1 * N + c]     = v0;
                C[(size_t)r1 * N + c + 1] = v1;
                C[(size_t)r2 * N + c]     = v2;
                C[(size_t)r2 * N + c + 1] = v3;
            }
        }
    }

    // ---- group-max epilogue (warp tile rows == one 32-row group) ----
    if (EPI >= 4) {
#pragma unroll
        for (int nt = 0; nt < 8; nt++) {
            const int c = col0 + wc + nt * 8 + lt * 2;
            float m0v = fmaxf(fmaxf(d[0][nt][0], d[0][nt][2]),
                              fmaxf(d[1][nt][0], d[1][nt][2]));
            float m1v = fmaxf(fmaxf(d[0][nt][1], d[0][nt][3]),
                              fmaxf(d[1][nt][1], d[1][nt][3]));
#pragma unroll
            for (int o = 4; o <= 16; o <<= 1) {
                m0v = fmaxf(m0v, __shfl_xor_sync(0xFFFFFFFFu, m0v, o));
                m1v = fmaxf(m1v, __shfl_xor_sync(0xFFFFFFFFu, m1v, o));
            }
            if (lane < 4) {
                if (bias) { m0v += bias[c]; m1v += bias[c + 1]; }
                float* gp = (EPI == 5) ? gout : C;
                gp[(size_t)g * N + c]     = m0v;
                gp[(size_t)g * N + c + 1] = m1v;
            }
        }
    }
}

// ============ attention QK: S = 0.125 * Q K^T (bf16x3 mma) ============
__global__ void __launch_bounds__(256) attn_qk_mma(const float* __restrict__ qkv,
                                                   float* __restrict__ S) {
    extern __shared__ uint32_t sm[];
    uint32_t* Ahi = sm;
    uint32_t* Alo = sm + 3072;
    uint32_t* Bhi = sm + 6144;
    uint32_t* Blo = sm + 9216;
    const int z = blockIdx.z;
    const int b = z / NH, h = z - b * NH;
    const float* Qb = qkv + (size_t)b * NG * 1152 + h * 64;
    const float* Kb = Qb + 384;
    const int m0 = blockIdx.y << 7, n0 = blockIdx.x << 7;
    const int tid = threadIdx.x;
    const int warp = tid >> 5, lane = tid & 31;
    const int wr = (warp & 3) << 5, wc = (warp >> 2) << 6;
    const int arow = tid >> 1, akoff = (tid & 1) << 4;
    const int lg = lane >> 2, lt = lane & 3;

    float d[2][8][4];
#pragma unroll
    for (int mt = 0; mt < 2; mt++)
#pragma unroll
        for (int nt = 0; nt < 8; nt++)
#pragma unroll
            for (int i = 0; i < 4; i++) d[mt][nt][i] = 0.f;

#pragma unroll
    for (int kb = 0; kb < 2; kb++) {
        const int kg = (kb << 5) + akoff;
        {
            const float* src = Qb + (size_t)(m0 + arow) * 1152 + kg;
            uint32_t* ah = Ahi + arow * AW + (akoff >> 4) * 8;
            uint32_t* al = Alo + arow * AW + (akoff >> 4) * 8;
            float v[16];
#pragma unroll
            for (int i = 0; i < 4; i++) *(float4*)&v[i * 4] = *(const float4*)&src[i * 4];
#pragma unroll
            for (int u = 0; u < 4; u++) {
                uint32_t h1, l1, h2, l2;
                bf16x2_split(v[2 * u], v[2 * u + 1], h1, l1);
                bf16x2_split(v[2 * u + 8], v[2 * u + 9], h2, l2);
                *(uint2*)(ah + 2 * u) = make_uint2(h1, h2);
                *(uint2*)(al + 2 * u) = make_uint2(l1, l2);
            }
        }
        {
            const float* src = Kb + (size_t)(n0 + arow) * 1152 + kg;
            uint32_t* bh = Bhi + arow * AW + (akoff >> 4) * 8;
            uint32_t* bl = Blo + arow * AW + (akoff >> 4) * 8;
            float v[16];
#pragma unroll
            for (int i = 0; i < 4; i++) *(float4*)&v[i * 4] = *(const float4*)&src[i * 4];
#pragma unroll
            for (int u = 0; u < 4; u++) {
                uint32_t h1, l1, h2, l2;
                bf16x2_split(v[2 * u], v[2 * u + 1], h1, l1);
                bf16x2_split(v[2 * u + 8], v[2 * u + 9], h2, l2);
                *(uint2*)(bh + 2 * u) = make_uint2(h1, h2);
                *(uint2*)(bl + 2 * u) = make_uint2(l1, l2);
            }
        }
        __syncthreads();
#pragma unroll
        for (int b16 = 0; b16 < 2; b16++) {
            const int bo = b16 * 8 + 2 * lt;
            uint32_t ah[2][4], al[2][4];
#pragma unroll
            for (int mt = 0; mt < 2; mt++) {
                const int r1 = wr + mt * 16 + lg;
                uint2 t0 = *(const uint2*)(Ahi + r1 * AW + bo);
                uint2 t1 = *(const uint2*)(Ahi + (r1 + 8) * AW + bo);
                ah[mt][0] = t0.x; ah[mt][1] = t1.x; ah[mt][2] = t0.y; ah[mt][3] = t1.y;
                uint2 s0 = *(const uint2*)(Alo + r1 * AW + bo);
                uint2 s1 = *(const uint2*)(Alo + (r1 + 8) * AW + bo);
                al[mt][0] = s0.x; al[mt][1] = s1.x; al[mt][2] = s0.y; al[mt][3] = s1.y;
            }
#pragma unroll
            for (int nt = 0; nt < 8; nt++) {
                const int n = wc + nt * 8 + lg;
                uint2 bh = *(const uint2*)(Bhi + n * AW + bo);
                uint2 bl = *(const uint2*)(Blo + n * AW + bo);
#pragma unroll
                for (int mt = 0; mt < 2; mt++) {
                    mma_bf16(d[mt][nt], ah[mt], bh.x, bh.y);
                    mma_bf16(d[mt][nt], al[mt], bh.x, bh.y);
                    mma_bf16(d[mt][nt], ah[mt], bl.x, bl.y);
                }
            }
        }
        __syncthreads();
    }
    float* out = S + (size_t)z * 512 * 512;
#pragma unroll
    for (int mt = 0; mt < 2; mt++) {
        const int r1 = m0 + wr + mt * 16 + lg;
        const int r2 = r1 + 8;
#pragma unroll
        for (int nt = 0; nt < 8; nt++) {
            const int c = n0 + wc + nt * 8 + lt * 2;
            out[(size_t)r1 * 512 + c]     = d[mt][nt][0] * 0.125f;
            out[(size_t)r1 * 512 + c + 1] = d[mt][nt][1] * 0.125f;
            out[(size_t)r2 * 512 + c]     = d[mt][nt][2] * 0.125f;
            out[(size_t)r2 * 512 + c + 1] = d[mt][nt][3] * 0.125f;
        }
    }
}

// ============ attention AV: O = A V (bf16x3 mma), tile 128x64 ============
__global__ void __launch_bounds__(256) attn_av_mma(const float* __restrict__ S,
                                                   const float* __restrict__ qkv,
                                                   float* __restrict__ O) {
    extern __shared__ uint32_t sm[];
    uint32_t* Ahi = sm;
    uint32_t* Alo = sm + 3072;
    uint32_t* Bhi = sm + 6144;
    uint32_t* Blo = sm + 6144 + 64 * AW;
    const int z = blockIdx.y;
    const int b = z / NH, h = z - b * NH;
    const float* A = S + (size_t)z * 512 * 512;
    const float* Vb = qkv + (size_t)b * NG * 1152 + 768 + h * 64;
    const int m0 = blockIdx.x << 7;
    const int tid = threadIdx.x;
    const int warp = tid >> 5, lane = tid & 31;
    const int wr = (warp & 3) << 5, wc = (warp >> 2) << 5;
    const int arow = tid >> 1, akoff = (tid & 1) << 4;
    const int bn = tid & 63, bhalf = (tid >> 6) & 1, brep = tid >> 7;
    const int lg = lane >> 2, lt = lane & 3;

    float d[2][4][4];
#pragma unroll
    for (int mt = 0; mt < 2; mt++)
#pragma unroll
        for (int nt = 0; nt < 4; nt++)
#pragma unroll
            for (int i = 0; i < 4; i++) d[mt][nt][i] = 0.f;

    for (int kb = 0; kb < 16; kb++) {
        const int kbase = kb << 5;
        {
            const float* src = A + (size_t)(m0 + arow) * 512 + kbase + akoff;
            uint32_t* ah = Ahi + arow * AW + (akoff >> 4) * 8;
            uint32_t* al = Alo + arow * AW + (akoff >> 4) * 8;
            float v[16];
#pragma unroll
            for (int i = 0; i < 4; i++) *(float4*)&v[i * 4] = *(const float4*)&src[i * 4];
#pragma unroll
            for (int u = 0; u < 4; u++) {
                uint32_t h1, l1, h2, l2;
                bf16x2_split(v[2 * u], v[2 * u + 1], h1, l1);
                bf16x2_split(v[2 * u + 8], v[2 * u + 9], h2, l2);
                *(uint2*)(ah + 2 * u) = make_uint2(h1, h2);
                *(uint2*)(al + 2 * u) = make_uint2(l1, l2);
            }
        }
        {
            uint32_t* bh = Bhi + bn * AW + bhalf * 8;
            uint32_t* bl = Blo + bn * AW + bhalf * 8;
#pragma unroll
            for (int p = 0; p < 4; p++) {
                const int k0 = kbase + bhalf * 16 + brep * 8 + 2 * p;
                float v0 = Vb[(size_t)k0 * 1152 + bn];
                float v1 = Vb[(size_t)(k0 + 1) * 1152 + bn];
                uint32_t hh, ll;
                bf16x2_split(v0, v1, hh, ll);
                bh[2 * p + brep] = hh;
                bl[2 * p + brep] = ll;
            }
        }
        __syncthreads();
#pragma unroll
        for (int b16 = 0; b16 < 2; b16++) {
            const int bo = b16 * 8 + 2 * lt;
            uint32_t ah[2][4], al[2][4];
#pragma unroll
            for (int mt = 0; mt < 2; mt++) {
                const int r1 = wr + mt * 16 + lg;
                uint2 t0 = *(const uint2*)(Ahi + r1 * AW + bo);
                uint2 t1 = *(const uint2*)(Ahi + (r1 + 8) * AW + bo);
                ah[mt][0] = t0.x; ah[mt][1] = t1.x; ah[mt][2] = t0.y; ah[mt][3] = t1.y;
                uint2 s0 = *(const uint2*)(Alo + r1 * AW + bo);
                uint2 s1 = *(const uint2*)(Alo + (r1 + 8) * AW + bo);
                al[mt][0] = s0.x; al[mt][1] = s1.x; al[mt][2] = s0.y; al[mt][3] = s1.y;
            }
#pragma unroll
            for (int nt = 0; nt < 4; nt++) {
                const int n = wc + nt * 8 + lg;
                uint2 bh = *(const uint2*)(Bhi + n * AW + bo);
                uint2 bl = *(const uint2*)(Blo + n * AW + bo);
#pragma unroll
                for (int mt = 0; mt < 2; mt++) {
                    mma_bf16(d[mt][nt], ah[mt], bh.x, bh.y);
                    mma_bf16(d[mt][nt], al[mt], bh.x, bh.y);
                    mma_bf16(d[mt][nt], ah[mt], bl.x, bl.y);
                }
            }
        }
        __syncthreads();
    }
    float* Ob = O + (size_t)b * NG * 384 + h * 64;
#pragma unroll
    for (int mt = 0; mt < 2; mt++) {
        const int r1 = m0 + wr + mt * 16 + lg;
        const int r2 = r1 + 8;
#pragma unroll
        for (int nt = 0; nt < 4; nt++) {
            const int c = wc + nt * 8 + lt * 2;
            Ob[(size_t)r1 * 384 + c]     = d[mt][nt][0];
            Ob[(size_t)r1 * 384 + c + 1] = d[mt][nt][1];
            Ob[(size_t)r2 * 384 + c]     = d[mt][nt][2];
            Ob[(size_t)r2 * 384 + c + 1] = d[mt][nt][3];
        }
    }
}

// ---------------- zero ----------------
__global__ void zero_kernel(float* p, int n) {
    int i = blockIdx.x * blockDim.x + threadIdx.x;
    if (i < n) p[i] = 0.0f;
}

// ---------------- FPS ----------------
__global__ void __launch_bounds__(1024) fps_kernel(const float* __restrict__ pts,
                                                   float* __restrict__ ctr,
                                                   float* __restrict__ ctr_out) {
    int b = blockIdx.x;
    int tid = threadIdx.x, wid = tid >> 5, lane = tid & 31;
    const float* P = pts + (size_t)b * NP * 3;
    float px[8], py[8], pz[8], dl[8];
#pragma unroll
    for (int t = 0; t < 8; t++) {
        int j = tid + t * 1024;
        px[t] = P[j * 3 + 0]; py[t] = P[j * 3 + 1]; pz[t] = P[j * 3 + 2];
        dl[t] = 1e10f;
    }
    __shared__ float lastp[3];
    __shared__ float wv_s[32];
    __shared__ int   wi_s[32];
    if (tid == 0) {
        lastp[0] = P[0]; lastp[1] = P[1]; lastp[2] = P[2];
        size_t co = (size_t)b * NG * 3;
        ctr[co] = P[0]; ctr[co + 1] = P[1]; ctr[co + 2] = P[2];
        ctr_out[co] = P[0]; ctr_out[co + 1] = P[1]; ctr_out[co + 2] = P[2];
    }
    __syncthreads();
    for (int s = 1; s < NG; s++) {
        float lx = lastp[0], ly = lastp[1], lz = lastp[2];
        float bv = -1.0f; int bi = 0;
#pragma unroll
        for (int t = 0; t < 8; t++) {
            float dx = __fsub_rn(px[t], lx);
            float dy = __fsub_rn(py[t], ly);
            float dz = __fsub_rn(pz[t], lz);
            float d = __fadd_rn(__fadd_rn(__fmul_rn(dx, dx), __fmul_rn(dy, dy)),
                                __fmul_rn(dz, dz));
            float nd = fminf(dl[t], d);
            dl[t] = nd;
            if (nd > bv) { bv = nd; bi = tid + t * 1024; }
        }
#pragma unroll
        for (int o = 16; o; o >>= 1) {
            float v2 = __shfl_xor_sync(0xFFFFFFFFu, bv, o);
            int   i2 = __shfl_xor_sync(0xFFFFFFFFu, bi, o);
            if (v2 > bv || (v2 == bv && i2 < bi)) { bv = v2; bi = i2; }
        }
        if (lane == 0) { wv_s[wid] = bv; wi_s[wid] = bi; }
        __syncthreads();
        if (wid == 0) {
            bv = wv_s[lane]; bi = wi_s[lane];
#pragma unroll
            for (int o = 16; o; o >>= 1) {
                float v2 = __shfl_xor_sync(0xFFFFFFFFu, bv, o);
                int   i2 = __shfl_xor_sync(0xFFFFFFFFu, bi, o);
                if (v2 > bv || (v2 == bv && i2 < bi)) { bv = v2; bi = i2; }
            }
            if (lane == 0) {
                float qx = P[bi * 3], qy = P[bi * 3 + 1], qz = P[bi * 3 + 2];
                lastp[0] = qx; lastp[1] = qy; lastp[2] = qz;
                size_t co = ((size_t)b * NG + s) * 3;
                ctr[co] = qx; ctr[co + 1] = qy; ctr[co + 2] = qz;
                ctr_out[co] = qx; ctr_out[co + 1] = qy; ctr_out[co + 2] = qz;
            }
        }
        __syncthreads();
    }
}

// ---------------- KNN ----------------
__global__ void __launch_bounds__(256) knn_kernel(const float* __restrict__ pts,
                                                  const float* __restrict__ ctr,
                                                  float* __restrict__ nbr_out) {
    int bg = blockIdx.x;
    int b = bg >> 9;
    const float* P = pts + (size_t)b * NP * 3;
    float cx = ctr[bg * 3 + 0], cy = ctr[bg * 3 + 1], cz = ctr[bg * 3 + 2];
    float c2 = __fadd_rn(__fadd_rn(__fmul_rn(cx, cx), __fmul_rn(cy, cy)), __fmul_rn(cz, cz));
    __shared__ float d2s[NP];
    int tid = threadIdx.x;
    for (int j = tid; j < NP; j += 256) {
        float px = P[j * 3], py = P[j * 3 + 1], pz = P[j * 3 + 2];
        float p2 = __fadd_rn(__fadd_rn(__fmul_rn(px, px), __fmul_rn(py, py)), __fmul_rn(pz, pz));
        float dot = __fmaf_rn(cz, pz, __fmaf_rn(cy, py, __fmul_rn(cx, px)));
        d2s[j] = __fsub_rn(__fadd_rn(c2, p2), __fmul_rn(2.0f, dot));
    }
    __syncthreads();
    __shared__ float rv[256];
    __shared__ int ri[256];
    __shared__ int chosen[NK];
    for (int sel = 0; sel < NK; sel++) {
        float bv = 3.4e38f; int bi = 0x7fffffff;
        for (int j = tid; j < NP; j += 256) {
            float v = d2s[j];
            if (v < bv) { bv = v; bi = j; }
        }
        rv[tid] = bv; ri[tid] = bi;
        __syncthreads();
        for (int o = 128; o; o >>= 1) {
            if (tid < o) {
                float v2 = rv[tid + o]; int i2 = ri[tid + o];
                if (v2 < rv[tid] || (v2 == rv[tid] && i2 < ri[tid])) {
                    rv[tid] = v2; ri[tid] = i2;
                }
            }
            __syncthreads();
        }
        if (tid == 0) { chosen[sel] = ri[0]; d2s[ri[0]] = 3.4e38f; }
        __syncthreads();
    }
    if (tid < NK) {
        int j = chosen[tid];
        size_t o = ((size_t)bg * NK + tid) * 3;
        nbr_out[o + 0] = P[j * 3 + 0] - cx;
        nbr_out[o + 1] = P[j * 3 + 1] - cy;
        nbr_out[o + 2] = P[j * 3 + 2] - cz;
    }
}

// ---------------- encoder first linear 3->128 ----------------
__global__ void enc1_kernel(const float* __restrict__ nbr, const float* __restrict__ w1,
                            const float* __restrict__ b1, float* __restrict__ h1) {
    size_t idx = (size_t)blockIdx.x * blockDim.x + threadIdx.x;
    if (idx >= (size_t)M1 * 128) return;
    size_t i = idx >> 7;
    int c = (int)(idx & 127);
    float x0 = nbr[i * 3], x1 = nbr[i * 3 + 1], x2 = nbr[i * 3 + 2];
    h1[idx] = x0 * w1[c] + x1 * w1[128 + c] + x2 * w1[256 + c] + b1[c];
}

// ---------------- BN stats ----------------
__global__ void bnstats_kernel(const float* __restrict__ h, int C,
                               float* __restrict__ s1, float* __restrict__ s2) {
    int c = threadIdx.x;
    size_t r0 = (size_t)blockIdx.x * 512;
    const float* p = h + r0 * C + c;
    float a = 0.f, q = 0.f;
    for (int r = 0; r < 512; r++) {
        float v = p[(size_t)r * C];
        a += v; q += v * v;
    }
    atomicAdd(&s1[c], a);
    atomicAdd(&s2[c], q);
}

__global__ void bnfin_kernel(const float* __restrict__ s1, const float* __restrict__ s2,
                             float invM, const float* __restrict__ g, const float* __restrict__ b,
                             float* __restrict__ scale, float* __restrict__ shift) {
    int c = threadIdx.x;
    float mean = s1[c] * invM;
    float var = s2[c] * invM - mean * mean;
    float r = rsqrtf(var + 1e-5f);
    float sc = g[c] * r;
    scale[c] = sc;
    shift[c] = b[c] - mean * sc;
}

// ---------------- layernorm ----------------
__global__ void __launch_bounds__(128) ln_kernel(const float* __restrict__ in,
                                                 float* __restrict__ out,
                                                 const float* __restrict__ gg,
                                                 const float* __restrict__ bb) {
    int row = blockIdx.x;
    int tid = threadIdx.x;
    const float* p = in + (size_t)row * 384;
    float v0 = p[tid], v1 = p[tid + 128], v2 = p[tid + 256];
    __shared__ float sh[128];
    sh[tid] = v0 + v1 + v2;
    __syncthreads();
    for (int o = 64; o; o >>= 1) { if (tid < o) sh[tid] += sh[tid + o]; __syncthreads(); }
    float mean = sh[0] * (1.0f / 384.0f);
    __syncthreads();
    float d0 = v0 - mean, d1 = v1 - mean, d2 = v2 - mean;
    sh[tid] = d0 * d0 + d1 * d1 + d2 * d2;
    __syncthreads();
    for (int o = 64; o; o >>= 1) { if (tid < o) sh[tid] += sh[tid + o]; __syncthreads(); }
    float rstd = rsqrtf(sh[0] * (1.0f / 384.0f) + 1e-5f);
    float* q = out + (size_t)row * 384;
    q[tid]       = d0 * rstd * gg[tid]       + bb[tid];
    q[tid + 128] = d1 * rstd * gg[tid + 128] + bb[tid + 128];
    q[tid + 256] = d2 * rstd * gg[tid + 256] + bb[tid + 256];
}

// xin = x + pos; out = LN(xin)
__global__ void __launch_bounds__(128) ln_add_kernel(const float* __restrict__ x,
                                                     const float* __restrict__ pos,
                                                     float* __restrict__ xin,
                                                     float* __restrict__ out,
                                                     const float* __restrict__ gg,
                                                     const float* __restrict__ bb) {
    int row = blockIdx.x;
    int tid = threadIdx.x;
    const float* p = x + (size_t)row * 384;
    const float* pp = pos + (size_t)row * 384;
    float v0 = p[tid] + pp[tid];
    float v1 = p[tid + 128] + pp[tid + 128];
    float v2 = p[tid + 256] + pp[tid + 256];
    float* xo = xin + (size_t)row * 384;
    xo[tid] = v0; xo[tid + 128] = v1; xo[tid + 256] = v2;
    __shared__ float sh[128];
    sh[tid] = v0 + v1 + v2;
    __syncthreads();
    for (int o = 64; o; o >>= 1) { if (tid < o) sh[tid] += sh[tid + o]; __syncthreads(); }
    float mean = sh[0] * (1.0f / 384.0f);
    __syncthreads();
    float d0 = v0 - mean, d1 = v1 - mean, d2 = v2 - mean;
    sh[tid] = d0 * d0 + d1 * d1 + d2 * d2;
    __syncthreads();
    for (int o = 64; o; o >>= 1) { if (tid < o) sh[tid] += sh[tid + o]; __syncthreads(); }
    float rstd = rsqrtf(sh[0] * (1.0f / 384.0f) + 1e-5f);
    float* q = out + (size_t)row * 384;
    q[tid]       = d0 * rstd * gg[tid]       + bb[tid];
    q[tid + 128] = d1 * rstd * gg[tid + 128] + bb[tid + 128];
    q[tid + 256] = d2 * rstd * gg[tid + 256] + bb[tid + 256];
}

// ---------------- pos embed ----------------
__global__ void __launch_bounds__(128) pos_kernel(const float* __restrict__ ctr,
                                                  const float* __restrict__ pw1,
                                                  const float* __restrict__ pb1,
                                                  const float* __restrict__ pw2,
                                                  const float* __restrict__ pb2,
                                                  float* __restrict__ pos) {
    int row = blockIdx.x;
    int tid = threadIdx.x;
    float cx = ctr[row * 3], cy = ctr[row * 3 + 1], cz = ctr[row * 3 + 2];
    __shared__ float t[128];
    float u = cx * pw1[tid] + cy * pw1[128 + tid] + cz * pw1[256 + tid] + pb1[tid];
    t[tid] = gelu_f(u);
    __syncthreads();
    for (int j = tid; j < 384; j += 128) {
        float s = pb2[j];
#pragma unroll 8
        for (int k = 0; k < 128; k++) s = fmaf(t[k], pw2[k * 384 + j], s);
        pos[(size_t)row * 384 + j] = s;
    }
}

__global__ void __launch_bounds__(128) softmax_kernel(float* __restrict__ S) {
    size_t row = blockIdx.x;
    float* p = S + row * 512;
    int tid = threadIdx.x;
    float v[4];
#pragma unroll
    for (int u = 0; u < 4; u++) v[u] = p[tid + u * 128];
    float m = fmaxf(fmaxf(v[0], v[1]), fmaxf(v[2], v[3]));
    __shared__ float sh[128];
    sh[tid] = m;
    __syncthreads();
    for (int o = 64; o; o >>= 1) { if (tid < o) sh[tid] = fmaxf(sh[tid], sh[tid + o]); __syncthreads(); }
    m = sh[0];
    __syncthreads();
    float s = 0.f;
#pragma unroll
    for (int u = 0; u < 4; u++) { v[u] = expf(v[u] - m); s += v[u]; }
    sh[tid] = s;
    __syncthreads();
    for (int o = 64; o; o >>= 1) { if (tid < o) sh[tid] += sh[tid + o]; __syncthreads(); }
    float inv = 1.0f / sh[0];
#pragma unroll
    for (int u = 0; u < 4; u++) p[tid + u * 128] = v[u] * inv;
}

// ---------------- host ----------------
extern "C" void kernel_launch(void* const* d_in, const int* in_sizes, int n_in,
                              void* d_out, int out_size) {
    const float* pts   = (const float*)d_in[0];
    const float* w1    = (const float*)d_in[1];
    const float* b1    = (const float*)d_in[2];
    const float* bn1g  = (const float*)d_in[3];
    const float* bn1b  = (const float*)d_in[4];
    const float* w2    = (const float*)d_in[5];
    const float* b2    = (const float*)d_in[6];
    const float* w3    = (const float*)d_in[7];
    const float* b3    = (const float*)d_in[8];
    const float* bn2g  = (const float*)d_in[9];
    const float* bn2b  = (const float*)d_in[10];
    const float* w4    = (const float*)d_in[11];
    const float* b4    = (const float*)d_in[12];
    const float* pw1   = (const float*)d_in[13];
    const float* pb1   = (const float*)d_in[14];
    const float* pw2   = (const float*)d_in[15];
    const float* pb2   = (const float*)d_in[16];
    const float* ln1g  = (const float*)d_in[17];
    const float* ln1b  = (const float*)d_in[18];
    const float* qkvw  = (const float*)d_in[19];
    const float* projw = (const float*)d_in[20];
    const float* projb = (const float*)d_in[21];
    const float* ln2g  = (const float*)d_in[22];
    const float* ln2b  = (const float*)d_in[23];
    const float* fc1w  = (const float*)d_in[24];
    const float* fc1b  = (const float*)d_in[25];
    const float* fc2w  = (const float*)d_in[26];
    const float* fc2b  = (const float*)d_in[27];
    const float* nfg   = (const float*)d_in[28];
    const float* nfb   = (const float*)d_in[29];

    static float* S = nullptr;
    if (!S) {
        cudaGetSymbolAddress((void**)&S, g_scratch);
        cudaFuncSetAttribute(mmagemm_kernel<0, 0>, cudaFuncAttributeMaxDynamicSharedMemorySize, GE_SMEM);
        cudaFuncSetAttribute(mmagemm_kernel<0, 1>, cudaFuncAttributeMaxDynamicSharedMemorySize, GE_SMEM);
        cudaFuncSetAttribute(mmagemm_kernel<0, 2>, cudaFuncAttributeMaxDynamicSharedMemorySize, GE_SMEM);
        cudaFuncSetAttribute(mmagemm_kernel<0, 3>, cudaFuncAttributeMaxDynamicSharedMemorySize, GE_SMEM);
        cudaFuncSetAttribute(mmagemm_kernel<1, 4>, cudaFuncAttributeMaxDynamicSharedMemorySize, GE_SMEM);
        cudaFuncSetAttribute(mmagemm_kernel<1, 5>, cudaFuncAttributeMaxDynamicSharedMemorySize, GE_SMEM);
        cudaFuncSetAttribute(attn_qk_mma, cudaFuncAttributeMaxDynamicSharedMemorySize, QK_SMEM);
        cudaFuncSetAttribute(attn_av_mma, cudaFuncAttributeMaxDynamicSharedMemorySize, AV_SMEM);
    }

    float* h1   = S + O_H1;
    float* f    = S + O_F;
    float* h3   = S + O_H3;
    float* fg   = S + O_FG;
    float* x    = S + O_X;
    float* xin  = S + O_XIN;
    float* hln  = S + O_HLN;
    float* ob   = S + O_OB;
    float* pos  = S + O_POS;
    float* qkv  = S + O_QKV;
    float* sc   = S + O_SC;
    float* ff   = S + O_FF;
    float* ctr  = S + O_CTR;
    float* st   = S + O_ST;
    float* s1a = st, *s2a = st + 128, *s1b = st + 256, *s2b = st + 768;
    float* scale1 = st + 1280, *shift1 = st + 1408;
    float* scale2 = st + 1536, *shift2 = st + 2048;

    float* out     = (float*)d_out;
    float* out_x   = out;                              // [16,512,384]
    float* out_nbr = out + (size_t)BGc * 384;          // [16,512,32,3]
    float* out_ctr = out_nbr + (size_t)BGc * NK * 3;   // [16,512,3]

    zero_kernel<<<16, 256>>>(st, 4096);

    fps_kernel<<<NB, 1024>>>(pts, ctr, out_ctr);
    knn_kernel<<<BGc, 256>>>(pts, ctr, out_nbr);

    enc1_kernel<<<(M1 * 128) / 256, 256>>>(out_nbr, w1, b1, h1);
    bnstats_kernel<<<M1 / 512, 128>>>(h1, 128, s1a, s2a);
    bnfin_kernel<<<1, 128>>>(s1a, s2a, 1.0f / (float)M1, bn1g, bn1b, scale1, shift1);
    // GEMM1: f = relu(bn(h1)) @ w2 + b2, fused group-max -> fg
    mmagemm_kernel<1, 5><<<dim3(2, 2048), 256, GE_SMEM>>>(h1, w2, b2, nullptr, f,
                                                          M1, 256, 128, scale1, shift1, fg);
    // base = fg @ w3[0:256] + b3  (per-group, tiny)
    mmagemm_kernel<0, 0><<<dim3(4, 64), 256, GE_SMEM>>>(fg, w3, b3, nullptr, ff,
                                                        BGc, 512, 256, nullptr, nullptr, nullptr);
    // h3 = f @ w3[256:512] + base[group]
    mmagemm_kernel<0, 3><<<dim3(4, 2048), 256, GE_SMEM>>>(f, w3 + 256 * 512, nullptr, ff, h3,
                                                          M1, 512, 256, nullptr, nullptr, nullptr);
    bnstats_kernel<<<M1 / 512, 512>>>(h3, 512, s1b, s2b);
    bnfin_kernel<<<1, 512>>>(s1b, s2b, 1.0f / (float)M1, bn2g, bn2b, scale2, shift2);
    // GEMM3: x[g] = max_k( relu(bn(h3)) @ w4 + b4 )  — group-max only epilogue
    mmagemm_kernel<1, 4><<<dim3(3, 2048), 256, GE_SMEM>>>(h3, w4, b4, nullptr, x,
                                                          M1, 384, 512, scale2, shift2, nullptr);

    pos_kernel<<<BGc, 128>>>(ctr, pw1, pb1, pw2, pb2, pos);

    for (int l = 0; l < NL; l++) {
        ln_add_kernel<<<BGc, 128>>>(x, pos, xin, hln, ln1g + l * 384, ln1b + l * 384);
        mmagemm_kernel<0, 0><<<dim3(9, 64), 256, GE_SMEM>>>(hln, qkvw + (size_t)l * 384 * 1152,
                                                            nullptr, nullptr, qkv, BGc, 1152, 384,
                                                            nullptr, nullptr, nullptr);
        attn_qk_mma<<<dim3(4, 4, NB * NH), 256, QK_SMEM>>>(qkv, sc);
        softmax_kernel<<<NB * NH * 512, 128>>>(sc);
        attn_av_mma<<<dim3(4, NB * NH), 256, AV_SMEM>>>(sc, qkv, ob);
        mmagemm_kernel<0, 1><<<dim3(3, 64), 256, GE_SMEM>>>(ob, projw + (size_t)l * 384 * 384,
                                                            projb + l * 384, xin, x, BGc, 384, 384,
                                                            nullptr, nullptr, nullptr);
        ln_kernel<<<BGc, 128>>>(x, hln, ln2g + l * 384, ln2b + l * 384);
        mmagemm_kernel<0, 2><<<dim3(12, 64), 256, GE_SMEM>>>(hln, fc1w + (size_t)l * 384 * 1536,
                                                             fc1b + l * 1536, nullptr, ff, BGc, 1536, 384,
                                                             nullptr, nullptr, nullptr);
        mmagemm_kernel<0, 1><<<dim3(3, 64), 256, GE_SMEM>>>(ff, fc2w + (size_t)l * 1536 * 384,
                                                            fc2b + l * 384, x, x, BGc, 384, 1536,
                                                            nullptr, nullptr, nullptr);
    }
    ln_kernel<<<BGc, 128>>>(x, out_x, nfg, nfb);
}